// round 2
// baseline (speedup 1.0000x reference)
#include <cuda_runtime.h>
#include <math.h>

#define EMB     1024
#define HEADS   16
#define HEAD_D  128
#define NB      2
#define SEQ     2048
#define OUTD    (HEADS * HEAD_D)   // 2048
#define M_TOTAL (NB * SEQ)         // 4096
#define PK      EMB                // GEMM K dim

// ---------------- scratch (allocation-free rule: __device__ globals) ----------
__device__ float g_Q[(size_t)NB * HEADS * SEQ * HEAD_D];
__device__ float g_K[(size_t)NB * HEADS * SEQ * HEAD_D];
__device__ float g_V[(size_t)NB * HEADS * SEQ * HEAD_D];

// ---------------- projection: out[(n,h,s,d)] = relu(X @ W^T + b) --------------
// X: (M_TOTAL, 1024) row-major, W: (2048, 1024) row-major (both K-contiguous)
__global__ __launch_bounds__(256, 1) void proj_kernel(
    const float* __restrict__ X, const float* __restrict__ W,
    const float* __restrict__ bias, float* __restrict__ out)
{
    __shared__ float As[16][132];
    __shared__ float Bs[16][132];

    const int tid = threadIdx.x;
    const int tx  = tid & 15;      // col group (8 cols each)
    const int ty  = tid >> 4;      // row group (8 rows each)
    const int lr  = tid >> 2;      // load row 0..63
    const int lc  = tid & 3;       // load k-vec 0..3

    const int rowBase = blockIdx.y * 128;
    const int colBase = blockIdx.x * 128;

    float acc[8][8];
    #pragma unroll
    for (int i = 0; i < 8; i++)
        #pragma unroll
        for (int j = 0; j < 8; j++) acc[i][j] = 0.f;

    for (int k0 = 0; k0 < PK; k0 += 16) {
        #pragma unroll
        for (int half = 0; half < 2; half++) {
            const int r = lr + half * 64;
            const float4 va = *(const float4*)(X + (size_t)(rowBase + r) * PK + k0 + lc * 4);
            As[lc*4+0][r] = va.x;
            As[lc*4+1][r] = va.y;
            As[lc*4+2][r] = va.z;
            As[lc*4+3][r] = va.w;
            const float4 vb = *(const float4*)(W + (size_t)(colBase + r) * PK + k0 + lc * 4);
            Bs[lc*4+0][r] = vb.x;
            Bs[lc*4+1][r] = vb.y;
            Bs[lc*4+2][r] = vb.z;
            Bs[lc*4+3][r] = vb.w;
        }
        __syncthreads();
        #pragma unroll
        for (int kk = 0; kk < 16; kk++) {
            float a[8], b[8];
            *(float4*)&a[0] = *(const float4*)&As[kk][ty * 8];
            *(float4*)&a[4] = *(const float4*)&As[kk][ty * 8 + 4];
            *(float4*)&b[0] = *(const float4*)&Bs[kk][tx * 8];
            *(float4*)&b[4] = *(const float4*)&Bs[kk][tx * 8 + 4];
            #pragma unroll
            for (int i = 0; i < 8; i++)
                #pragma unroll
                for (int j = 0; j < 8; j++)
                    acc[i][j] = fmaf(a[i], b[j], acc[i][j]);
        }
        __syncthreads();
    }

    // epilogue: bias + relu, store into (n, h, s, d)
    const int c0 = colBase + tx * 8;
    const int h  = c0 >> 7;          // head index (c0 aligned to 8, <128 within head)
    const int d0 = c0 & 127;
    float bv[8];
    #pragma unroll
    for (int j = 0; j < 8; j++) bv[j] = bias[c0 + j];

    #pragma unroll
    for (int i = 0; i < 8; i++) {
        const int m  = rowBase + ty * 8 + i;
        const int nb = m >> 11;        // SEQ = 2048
        const int s  = m & 2047;
        float* op = out + (((size_t)(nb * HEADS + h)) * SEQ + s) * HEAD_D + d0;
        float4 r0, r1;
        r0.x = fmaxf(acc[i][0] + bv[0], 0.f);
        r0.y = fmaxf(acc[i][1] + bv[1], 0.f);
        r0.z = fmaxf(acc[i][2] + bv[2], 0.f);
        r0.w = fmaxf(acc[i][3] + bv[3], 0.f);
        r1.x = fmaxf(acc[i][4] + bv[4], 0.f);
        r1.y = fmaxf(acc[i][5] + bv[5], 0.f);
        r1.z = fmaxf(acc[i][6] + bv[6], 0.f);
        r1.w = fmaxf(acc[i][7] + bv[7], 0.f);
        *(float4*)(op)     = r0;
        *(float4*)(op + 4) = r1;
    }
}

// ---------------- attention (flash-style, fp32) -------------------------------
#define BQ        64
#define BKV       64
#define KQ_STRIDE 129   // Qs / Ks row stride (scalar access, bank-friendly)
#define V_STRIDE  132   // Vs row stride (float4 access)
#define P_STRIDE  68

__global__ __launch_bounds__(256, 1) void attn_kernel(
    const float* __restrict__ Q, const float* __restrict__ K,
    const float* __restrict__ V, const int* __restrict__ mask,
    float* __restrict__ out)
{
    extern __shared__ float sm[];
    float* Qs = sm;                            // BQ  x KQ_STRIDE
    float* Ks = Qs + BQ * KQ_STRIDE;           // BKV x KQ_STRIDE
    float* Vs = Ks + BKV * KQ_STRIDE;          // BKV x V_STRIDE
    float* Ps = Vs + BKV * V_STRIDE;           // BQ  x P_STRIDE

    const int tid = threadIdx.x;
    const int tx  = tid & 15;    // 4 score-cols / 8 d-cols
    const int ty  = tid >> 4;    // 4 rows
    const int n   = blockIdx.z;
    const int h   = blockIdx.y;
    const int qt  = blockIdx.x;

    const float* Qg = Q + (((size_t)(n * HEADS + h)) * SEQ + qt * BQ) * HEAD_D;
    const float* Kg = K + (((size_t)(n * HEADS + h)) * SEQ) * HEAD_D;
    const float* Vg = V + (((size_t)(n * HEADS + h)) * SEQ) * HEAD_D;

    // load Q tile (64 x 128)
    for (int i = tid; i < BQ * 32; i += 256) {
        const int r = i >> 5, c = i & 31;
        const float4 v = *(const float4*)(Qg + r * HEAD_D + c * 4);
        float* p = Qs + r * KQ_STRIDE + c * 4;
        p[0] = v.x; p[1] = v.y; p[2] = v.z; p[3] = v.w;
    }

    float mi[4], li[4], O[4][8];
    #pragma unroll
    for (int i = 0; i < 4; i++) {
        mi[i] = -1e30f;
        li[i] = 0.f;
        #pragma unroll
        for (int j = 0; j < 8; j++) O[i][j] = 0.f;
    }

    const float scale = 0.08838834764831845f;   // 1/sqrt(128)
    const int q0 = qt * BQ + ty * 4;

    for (int kt = 0; kt < SEQ / BKV; kt++) {
        __syncthreads();   // previous iter's PV done (also covers Q load on iter 0)

        // load K, V tiles (64 x 128 each)
        const float* Kt = Kg + (size_t)kt * BKV * HEAD_D;
        const float* Vt = Vg + (size_t)kt * BKV * HEAD_D;
        for (int i = tid; i < BKV * 32; i += 256) {
            const int r = i >> 5, c = i & 31;
            const float4 vk = *(const float4*)(Kt + r * HEAD_D + c * 4);
            float* pk = Ks + r * KQ_STRIDE + c * 4;
            pk[0] = vk.x; pk[1] = vk.y; pk[2] = vk.z; pk[3] = vk.w;
            const float4 vv = *(const float4*)(Vt + r * HEAD_D + c * 4);
            float* pv = Vs + r * V_STRIDE + c * 4;
            pv[0] = vv.x; pv[1] = vv.y; pv[2] = vv.z; pv[3] = vv.w;
        }
        __syncthreads();

        // S = Q K^T (64x64 tile; each thread 4x4)
        float sacc[4][4];
        #pragma unroll
        for (int i = 0; i < 4; i++)
            #pragma unroll
            for (int j = 0; j < 4; j++) sacc[i][j] = 0.f;

        #pragma unroll 4
        for (int d = 0; d < HEAD_D; d++) {
            float a[4], b[4];
            #pragma unroll
            for (int i = 0; i < 4; i++) a[i] = Qs[(ty * 4 + i) * KQ_STRIDE + d];
            #pragma unroll
            for (int j = 0; j < 4; j++) b[j] = Ks[(tx * 4 + j) * KQ_STRIDE + d];
            #pragma unroll
            for (int i = 0; i < 4; i++)
                #pragma unroll
                for (int j = 0; j < 4; j++)
                    sacc[i][j] = fmaf(a[i], b[j], sacc[i][j]);
        }

        // scale + mask
        const int k0g = kt * BKV + tx * 4;
        #pragma unroll
        for (int i = 0; i < 4; i++) {
            const int* mrow = mask + (size_t)(q0 + i) * SEQ + k0g;
            #pragma unroll
            for (int j = 0; j < 4; j++) {
                const float sv = sacc[i][j] * scale;
                sacc[i][j] = (mrow[j] == 0) ? -1e7f : sv;
            }
        }

        // online softmax (row reductions across the 16-lane tx groups)
        #pragma unroll
        for (int i = 0; i < 4; i++) {
            float rm = fmaxf(fmaxf(sacc[i][0], sacc[i][1]),
                             fmaxf(sacc[i][2], sacc[i][3]));
            #pragma unroll
            for (int off = 8; off >= 1; off >>= 1)
                rm = fmaxf(rm, __shfl_xor_sync(0xffffffffu, rm, off));
            const float newm = fmaxf(mi[i], rm);
            const float corr = __expf(mi[i] - newm);
            float rs = 0.f;
            #pragma unroll
            for (int j = 0; j < 4; j++) {
                const float e = __expf(sacc[i][j] - newm);
                sacc[i][j] = e;
                rs += e;
            }
            #pragma unroll
            for (int off = 8; off >= 1; off >>= 1)
                rs += __shfl_xor_sync(0xffffffffu, rs, off);
            li[i] = li[i] * corr + rs;
            mi[i] = newm;
            #pragma unroll
            for (int jj = 0; jj < 8; jj++) O[i][jj] *= corr;
        }

        // stage P
        #pragma unroll
        for (int i = 0; i < 4; i++)
            #pragma unroll
            for (int j = 0; j < 4; j++)
                Ps[(ty * 4 + i) * P_STRIDE + tx * 4 + j] = sacc[i][j];
        __syncthreads();

        // O += P @ V  (each thread: 4 rows x 8 d-cols, d = tx*8..)
        #pragma unroll 2
        for (int j = 0; j < BKV; j++) {
            float p[4];
            #pragma unroll
            for (int i = 0; i < 4; i++) p[i] = Ps[(ty * 4 + i) * P_STRIDE + j];
            float v[8];
            *(float4*)&v[0] = *(const float4*)&Vs[j * V_STRIDE + tx * 8];
            *(float4*)&v[4] = *(const float4*)&Vs[j * V_STRIDE + tx * 8 + 4];
            #pragma unroll
            for (int i = 0; i < 4; i++)
                #pragma unroll
                for (int jj = 0; jj < 8; jj++)
                    O[i][jj] = fmaf(p[i], v[jj], O[i][jj]);
        }
    }

    // epilogue: normalize, write out[n][s][h*128 + d]
    #pragma unroll
    for (int i = 0; i < 4; i++) {
        const float inv = 1.0f / li[i];
        const int s = qt * BQ + ty * 4 + i;
        float* op = out + ((size_t)n * SEQ + s) * OUTD + h * HEAD_D + tx * 8;
        float4 r0, r1;
        r0.x = O[i][0] * inv; r0.y = O[i][1] * inv;
        r0.z = O[i][2] * inv; r0.w = O[i][3] * inv;
        r1.x = O[i][4] * inv; r1.y = O[i][5] * inv;
        r1.z = O[i][6] * inv; r1.w = O[i][7] * inv;
        *(float4*)(op)     = r0;
        *(float4*)(op + 4) = r1;
    }
}

// ---------------- launch -------------------------------------------------------
extern "C" void kernel_launch(void* const* d_in, const int* in_sizes, int n_in,
                              void* d_out, int out_size)
{
    const float* query = (const float*)d_in[0];
    const float* key   = (const float*)d_in[1];
    const float* value = (const float*)d_in[2];
    const int*   mask  = (const int*)d_in[3];
    const float* Wq    = (const float*)d_in[4];
    const float* bq    = (const float*)d_in[5];
    const float* Wk    = (const float*)d_in[6];
    const float* bk    = (const float*)d_in[7];
    const float* Wv    = (const float*)d_in[8];
    const float* bv    = (const float*)d_in[9];
    float* out = (float*)d_out;

    float *qb = nullptr, *kb = nullptr, *vb = nullptr;
    cudaGetSymbolAddress((void**)&qb, g_Q);
    cudaGetSymbolAddress((void**)&kb, g_K);
    cudaGetSymbolAddress((void**)&vb, g_V);

    dim3 pgrid(OUTD / 128, M_TOTAL / 128);
    proj_kernel<<<pgrid, 256>>>(query, Wq, bq, qb);
    proj_kernel<<<pgrid, 256>>>(key,   Wk, bk, kb);
    proj_kernel<<<pgrid, 256>>>(value, Wv, bv, vb);

    const size_t attn_smem =
        (size_t)(BQ * KQ_STRIDE + BKV * KQ_STRIDE + BKV * V_STRIDE + BQ * P_STRIDE)
        * sizeof(float);
    cudaFuncSetAttribute(attn_kernel, cudaFuncAttributeMaxDynamicSharedMemorySize,
                         (int)attn_smem);
    dim3 agrid(SEQ / BQ, HEADS, NB);
    attn_kernel<<<agrid, 256, attn_smem>>>(qb, kb, vb, mask, out);
}

// round 3
// speedup vs baseline: 1.3162x; 1.3162x over previous
#include <cuda_runtime.h>
#include <mma.h>
#include <math.h>

using namespace nvcuda;

#define EMB     1024
#define HEADS   16
#define HEAD_D  128
#define NB      2
#define SEQ     2048
#define OUTD    (HEADS * HEAD_D)   // 2048
#define M_TOTAL (NB * SEQ)         // 4096
#define PK      EMB

// ---------------- scratch ------------------------------------------------------
__device__ float g_Q[(size_t)NB * HEADS * SEQ * HEAD_D];
__device__ float g_K[(size_t)NB * HEADS * SEQ * HEAD_D];
__device__ float g_V[(size_t)NB * HEADS * SEQ * HEAD_D];

typedef wmma::fragment<wmma::matrix_a, 16, 16, 8, wmma::precision::tf32, wmma::row_major> FragA;
typedef wmma::fragment<wmma::matrix_b, 16, 16, 8, wmma::precision::tf32, wmma::col_major> FragBc;
typedef wmma::fragment<wmma::matrix_b, 16, 16, 8, wmma::precision::tf32, wmma::row_major> FragBr;
typedef wmma::fragment<wmma::accumulator, 16, 16, 8, float> FragC;

__device__ __forceinline__ void cvt_tf32(float* x, int n) {
    for (int i = 0; i < n; i++) x[i] = wmma::__float_to_tf32(x[i]);
}

// ---------------- projection: out[(n,h,s,d)] = relu(X @ W^T + b) ---------------
// wmma tf32, 128x128 block tile, BK=32, 8 warps (warp tile 32x64)
#define P_AS 36    // A smem row stride (floats)
#define P_CS 132   // C staging row stride

__global__ __launch_bounds__(256) void proj_kernel(
    const float* __restrict__ X, const float* __restrict__ W,
    const float* __restrict__ bias, float* __restrict__ out)
{
    extern __shared__ float sm[];
    float* As = sm;                 // 128 x P_AS
    float* Bs = sm + 128 * P_AS;    // 128 x P_AS
    float* Cs = sm;                 // 128 x P_CS (reused after mainloop)

    const int tid    = threadIdx.x;
    const int warp   = tid >> 5;
    const int warp_m = warp >> 1;   // 0..3
    const int warp_n = warp & 1;    // 0..1
    const int rowBase = blockIdx.y * 128;
    const int colBase = blockIdx.x * 128;

    FragC acc[2][4];
    #pragma unroll
    for (int i = 0; i < 2; i++)
        #pragma unroll
        for (int j = 0; j < 4; j++) wmma::fill_fragment(acc[i][j], 0.0f);

    for (int k0 = 0; k0 < PK; k0 += 32) {
        // load A (128x32) and B (128x32) tiles
        #pragma unroll
        for (int it = 0; it < 4; it++) {
            const int f   = tid + 256 * it;      // float4 index, 1024 total
            const int row = f >> 3;
            const int c4  = (f & 7) * 4;
            const float4 va = *(const float4*)(X + (size_t)(rowBase + row) * PK + k0 + c4);
            *(float4*)(As + row * P_AS + c4) = va;
            const float4 vb = *(const float4*)(W + (size_t)(colBase + row) * PK + k0 + c4);
            *(float4*)(Bs + row * P_AS + c4) = vb;
        }
        __syncthreads();

        #pragma unroll
        for (int kk = 0; kk < 32; kk += 8) {
            FragA a[2];
            #pragma unroll
            for (int i = 0; i < 2; i++) {
                wmma::load_matrix_sync(a[i], As + (warp_m * 32 + 16 * i) * P_AS + kk, P_AS);
                cvt_tf32(a[i].x, a[i].num_elements);
            }
            #pragma unroll
            for (int j = 0; j < 4; j++) {
                FragBc b;
                wmma::load_matrix_sync(b, Bs + (warp_n * 64 + 16 * j) * P_AS + kk, P_AS);
                cvt_tf32(b.x, b.num_elements);
                #pragma unroll
                for (int i = 0; i < 2; i++)
                    wmma::mma_sync(acc[i][j], a[i], b, acc[i][j]);
            }
        }
        __syncthreads();
    }

    // stage C to smem
    #pragma unroll
    for (int i = 0; i < 2; i++)
        #pragma unroll
        for (int j = 0; j < 4; j++)
            wmma::store_matrix_sync(
                Cs + (warp_m * 32 + 16 * i) * P_CS + warp_n * 64 + 16 * j,
                acc[i][j], P_CS, wmma::mem_row_major);
    __syncthreads();

    // bias + relu + scatter to (n,h,s,d)
    const int h = colBase >> 7;   // HEAD_D == 128 == block N-tile
    #pragma unroll
    for (int it = 0; it < 16; it++) {
        const int f   = tid + 256 * it;   // float4 index over 128x128
        const int row = f >> 5;
        const int c4  = (f & 31) * 4;
        float4 v = *(const float4*)(Cs + row * P_CS + c4);
        const float4 bv = *(const float4*)(bias + colBase + c4);
        v.x = fmaxf(v.x + bv.x, 0.f);
        v.y = fmaxf(v.y + bv.y, 0.f);
        v.z = fmaxf(v.z + bv.z, 0.f);
        v.w = fmaxf(v.w + bv.w, 0.f);
        const int m  = rowBase + row;
        const int nb = m >> 11;
        const int s  = m & 2047;
        *(float4*)(out + (((size_t)(nb * HEADS + h)) * SEQ + s) * HEAD_D + c4) = v;
    }
}

// ---------------- attention (wmma tf32, no-max softmax) ------------------------
#define BQ   64
#define BKV  64
#define A_QS 132
#define A_PS 68

__global__ __launch_bounds__(256) void attn_kernel(
    const float* __restrict__ Q, const float* __restrict__ K,
    const float* __restrict__ V, const int* __restrict__ mask,
    float* __restrict__ out)
{
    extern __shared__ float sm[];
    float* Qs = sm;                       // 64 x 132
    float* Ks = Qs + BQ * A_QS;           // 64 x 132
    float* Vs = Ks + BKV * A_QS;          // 64 x 132
    float* Ps = Vs + BKV * A_QS;          // 64 x 68
    float* Ls = Ps + BQ * A_PS;           // 64

    const int tid    = threadIdx.x;
    const int warp   = tid >> 5;
    const int warp_m = warp >> 1;   // 0..3 (q-row block of 16)
    const int warp_n = warp & 1;    // 0..1
    const int n  = blockIdx.z;
    const int h  = blockIdx.y;
    const int qt = blockIdx.x;

    const float* Qg = Q + (((size_t)(n * HEADS + h)) * SEQ + qt * BQ) * HEAD_D;
    const float* Kg = K + (((size_t)(n * HEADS + h)) * SEQ) * HEAD_D;
    const float* Vg = V + (((size_t)(n * HEADS + h)) * SEQ) * HEAD_D;

    // load Q tile, init L
    #pragma unroll
    for (int it = 0; it < 8; it++) {
        const int f   = tid + 256 * it;     // 2048 float4s
        const int row = f >> 5;
        const int c4  = (f & 31) * 4;
        *(float4*)(Qs + row * A_QS + c4) = *(const float4*)(Qg + row * HEAD_D + c4);
    }
    if (tid < BQ) Ls[tid] = 0.f;
    __syncthreads();

    FragC oacc[4];   // O tile: rows warp_m*16, cols warp_n*64 (4 x 16-wide)
    #pragma unroll
    for (int j = 0; j < 4; j++) wmma::fill_fragment(oacc[j], 0.0f);

    const float scale = 0.08838834764831845f;   // 1/sqrt(128)
    const int q0 = qt * BQ;

    for (int kt = 0; kt < SEQ / BKV; kt++) {
        // load K, V tiles
        const float* Kt = Kg + (size_t)kt * BKV * HEAD_D;
        const float* Vt = Vg + (size_t)kt * BKV * HEAD_D;
        #pragma unroll
        for (int it = 0; it < 8; it++) {
            const int f   = tid + 256 * it;
            const int row = f >> 5;
            const int c4  = (f & 31) * 4;
            *(float4*)(Ks + row * A_QS + c4) = *(const float4*)(Kt + row * HEAD_D + c4);
            *(float4*)(Vs + row * A_QS + c4) = *(const float4*)(Vt + row * HEAD_D + c4);
        }
        __syncthreads();

        // S = Q @ K^T : warp computes 16 x 32 (2 frags), k over 128
        FragC sacc[2];
        wmma::fill_fragment(sacc[0], 0.0f);
        wmma::fill_fragment(sacc[1], 0.0f);
        #pragma unroll
        for (int d = 0; d < HEAD_D; d += 8) {
            FragA a;
            wmma::load_matrix_sync(a, Qs + (warp_m * 16) * A_QS + d, A_QS);
            cvt_tf32(a.x, a.num_elements);
            #pragma unroll
            for (int j = 0; j < 2; j++) {
                FragBc b;
                wmma::load_matrix_sync(b, Ks + (warp_n * 32 + 16 * j) * A_QS + d, A_QS);
                cvt_tf32(b.x, b.num_elements);
                wmma::mma_sync(sacc[j], a, b, sacc[j]);
            }
        }
        #pragma unroll
        for (int j = 0; j < 2; j++)
            wmma::store_matrix_sync(Ps + (warp_m * 16) * A_PS + warp_n * 32 + 16 * j,
                                    sacc[j], A_PS, wmma::mem_row_major);
        __syncthreads();

        // softmax numerator: exp(scale*s) with mask, accumulate row sums
        {
            const int row = tid >> 2;          // 0..63
            const int seg = (tid & 3) * 16;    // 16 cols each
            float* prow = Ps + row * A_PS + seg;
            const int* mrow = mask + (size_t)(q0 + row) * SEQ + kt * BKV + seg;
            float psum = 0.f;
            #pragma unroll
            for (int c = 0; c < 16; c += 4) {
                const int4 mv = *(const int4*)(mrow + c);
                float e0 = (mv.x == 0) ? 0.f : __expf(prow[c + 0] * scale);
                float e1 = (mv.y == 0) ? 0.f : __expf(prow[c + 1] * scale);
                float e2 = (mv.z == 0) ? 0.f : __expf(prow[c + 2] * scale);
                float e3 = (mv.w == 0) ? 0.f : __expf(prow[c + 3] * scale);
                prow[c + 0] = e0; prow[c + 1] = e1;
                prow[c + 2] = e2; prow[c + 3] = e3;
                psum += e0 + e1 + e2 + e3;
            }
            psum += __shfl_xor_sync(0xffffffffu, psum, 1);
            psum += __shfl_xor_sync(0xffffffffu, psum, 2);
            if ((tid & 3) == 0) Ls[row] += psum;
        }
        __syncthreads();

        // O += P @ V : warp computes rows warp_m*16, cols warp_n*64
        #pragma unroll
        for (int k = 0; k < BKV; k += 8) {
            FragA a;
            wmma::load_matrix_sync(a, Ps + (warp_m * 16) * A_PS + k, A_PS);
            cvt_tf32(a.x, a.num_elements);
            #pragma unroll
            for (int j = 0; j < 4; j++) {
                FragBr b;
                wmma::load_matrix_sync(b, Vs + k * A_QS + warp_n * 64 + 16 * j, A_QS);
                cvt_tf32(b.x, b.num_elements);
                wmma::mma_sync(oacc[j], a, b, oacc[j]);
            }
        }
        __syncthreads();   // before next K/V overwrite (and Ps overwrite)
    }

    // stage O into Ks region, normalize, write out
    #pragma unroll
    for (int j = 0; j < 4; j++)
        wmma::store_matrix_sync(Ks + (warp_m * 16) * A_QS + warp_n * 64 + 16 * j,
                                oacc[j], A_QS, wmma::mem_row_major);
    __syncthreads();

    #pragma unroll
    for (int it = 0; it < 8; it++) {
        const int f   = tid + 256 * it;    // 2048 float4s over 64x128
        const int row = f >> 5;
        const int c4  = (f & 31) * 4;
        const float inv = 1.0f / Ls[row];
        float4 v = *(const float4*)(Ks + row * A_QS + c4);
        v.x *= inv; v.y *= inv; v.z *= inv; v.w *= inv;
        const int s = q0 + row;
        *(float4*)(out + ((size_t)n * SEQ + s) * OUTD + h * HEAD_D + c4) = v;
    }
}

// ---------------- launch --------------------------------------------------------
extern "C" void kernel_launch(void* const* d_in, const int* in_sizes, int n_in,
                              void* d_out, int out_size)
{
    const float* query = (const float*)d_in[0];
    const float* key   = (const float*)d_in[1];
    const float* value = (const float*)d_in[2];
    const int*   mask  = (const int*)d_in[3];
    const float* Wq    = (const float*)d_in[4];
    const float* bq    = (const float*)d_in[5];
    const float* Wk    = (const float*)d_in[6];
    const float* bk    = (const float*)d_in[7];
    const float* Wv    = (const float*)d_in[8];
    const float* bv    = (const float*)d_in[9];
    float* out = (float*)d_out;

    float *qb = nullptr, *kb = nullptr, *vb = nullptr;
    cudaGetSymbolAddress((void**)&qb, g_Q);
    cudaGetSymbolAddress((void**)&kb, g_K);
    cudaGetSymbolAddress((void**)&vb, g_V);

    const int proj_smem = 128 * P_CS * sizeof(float);   // 67584 B (>= A+B region)
    cudaFuncSetAttribute(proj_kernel, cudaFuncAttributeMaxDynamicSharedMemorySize,
                         proj_smem);
    dim3 pgrid(OUTD / 128, M_TOTAL / 128);
    proj_kernel<<<pgrid, 256, proj_smem>>>(query, Wq, bq, qb);
    proj_kernel<<<pgrid, 256, proj_smem>>>(key,   Wk, bk, kb);
    proj_kernel<<<pgrid, 256, proj_smem>>>(value, Wv, bv, vb);

    const int attn_smem =
        (3 * BQ * A_QS + BQ * A_PS + BQ) * sizeof(float);   // 119,296 B
    cudaFuncSetAttribute(attn_kernel, cudaFuncAttributeMaxDynamicSharedMemorySize,
                         attn_smem);
    dim3 agrid(SEQ / BQ, HEADS, NB);
    attn_kernel<<<agrid, 256, attn_smem>>>(qb, kb, vb, mask, out);
}

// round 4
// speedup vs baseline: 2.7109x; 2.0597x over previous
#include <cuda_runtime.h>
#include <cuda_bf16.h>
#include <mma.h>
#include <math.h>

using namespace nvcuda;

#define EMB     1024
#define HEADS   16
#define HEAD_D  128
#define NB      2
#define SEQ     2048
#define OUTD    (HEADS * HEAD_D)   // 2048
#define M_TOTAL (NB * SEQ)         // 4096
#define PK      EMB

// ---------------- scratch ------------------------------------------------------
__device__ __nv_bfloat16 g_Q[(size_t)NB * HEADS * SEQ * HEAD_D];
__device__ __nv_bfloat16 g_K[(size_t)NB * HEADS * SEQ * HEAD_D];
__device__ __nv_bfloat16 g_V[(size_t)NB * HEADS * SEQ * HEAD_D];
__device__ unsigned      g_mbits[SEQ * (SEQ / 32)];   // packed mask bits

// tf32 frags (projection)
typedef wmma::fragment<wmma::matrix_a, 16, 16, 8, wmma::precision::tf32, wmma::row_major> TFragA;
typedef wmma::fragment<wmma::matrix_b, 16, 16, 8, wmma::precision::tf32, wmma::col_major> TFragB;
// bf16 frags (attention)
typedef wmma::fragment<wmma::matrix_a, 16, 16, 16, __nv_bfloat16, wmma::row_major> BFragA;
typedef wmma::fragment<wmma::matrix_b, 16, 16, 16, __nv_bfloat16, wmma::col_major> BFragBc;
typedef wmma::fragment<wmma::matrix_b, 16, 16, 16, __nv_bfloat16, wmma::row_major> BFragBr;
typedef wmma::fragment<wmma::accumulator, 16, 16, 16, float> BFragC;
typedef wmma::fragment<wmma::accumulator, 16, 16, 8,  float> TFragC;

__device__ __forceinline__ void cvt_tf32(float* x, int n) {
    for (int i = 0; i < n; i++) x[i] = wmma::__float_to_tf32(x[i]);
}

__device__ __forceinline__ void cp16(void* dst, const void* src) {
    unsigned d = (unsigned)__cvta_generic_to_shared(dst);
    asm volatile("cp.async.cg.shared.global [%0], [%1], 16;\n" :: "r"(d), "l"(src));
}
#define CP_COMMIT() asm volatile("cp.async.commit_group;\n" ::: "memory")
#define CP_WAIT(n)  asm volatile("cp.async.wait_group %0;\n" :: "n"(n) : "memory")

// ---------------- mask packing -------------------------------------------------
__global__ void pack_mask_kernel(const int* __restrict__ mask, unsigned* __restrict__ bits)
{
    const int e = blockIdx.x * 256 + threadIdx.x;   // over SEQ*SEQ
    const unsigned b = __ballot_sync(0xffffffffu, mask[e] != 0);
    if ((threadIdx.x & 31) == 0) bits[e >> 5] = b;
}

// ---------------- projection: out[(n,h,s,d)] = relu(X @ W^T + b), bf16 out ------
#define P_AS 36
#define P_CS 132

__global__ __launch_bounds__(256, 2) void proj_kernel(
    const float* __restrict__ X, const float* __restrict__ W,
    const float* __restrict__ bias, __nv_bfloat16* __restrict__ out)
{
    extern __shared__ float sm[];
    // double-buffered A/B stages; epilogue Cs overlays the same region
    float* As[2] = { sm,                 sm + 2 * 128 * P_AS };
    float* Bs[2] = { sm + 128 * P_AS,    sm + 3 * 128 * P_AS };
    float* Cs = sm;

    const int tid    = threadIdx.x;
    const int warp   = tid >> 5;
    const int warp_m = warp >> 1;
    const int warp_n = warp & 1;
    const int rowBase = blockIdx.y * 128;
    const int colBase = blockIdx.x * 128;

    TFragC acc[2][4];
    #pragma unroll
    for (int i = 0; i < 2; i++)
        #pragma unroll
        for (int j = 0; j < 4; j++) wmma::fill_fragment(acc[i][j], 0.0f);

    const int NIT = PK / 32;   // 32

    // preload stage 0
    #pragma unroll
    for (int it = 0; it < 4; it++) {
        const int f = tid + 256 * it;
        const int row = f >> 3, c4 = (f & 7) * 4;
        cp16(As[0] + row * P_AS + c4, X + (size_t)(rowBase + row) * PK + c4);
        cp16(Bs[0] + row * P_AS + c4, W + (size_t)(colBase + row) * PK + c4);
    }
    CP_COMMIT();

    for (int i = 0; i < NIT; i++) {
        if (i + 1 < NIT) {
            const int k0 = (i + 1) * 32;
            float* an = As[(i + 1) & 1];
            float* bn = Bs[(i + 1) & 1];
            #pragma unroll
            for (int it = 0; it < 4; it++) {
                const int f = tid + 256 * it;
                const int row = f >> 3, c4 = (f & 7) * 4;
                cp16(an + row * P_AS + c4, X + (size_t)(rowBase + row) * PK + k0 + c4);
                cp16(bn + row * P_AS + c4, W + (size_t)(colBase + row) * PK + k0 + c4);
            }
            CP_COMMIT();
            CP_WAIT(1);
        } else {
            CP_WAIT(0);
        }
        __syncthreads();

        float* ac = As[i & 1];
        float* bc = Bs[i & 1];
        #pragma unroll
        for (int kk = 0; kk < 32; kk += 8) {
            TFragA a[2];
            #pragma unroll
            for (int r = 0; r < 2; r++) {
                wmma::load_matrix_sync(a[r], ac + (warp_m * 32 + 16 * r) * P_AS + kk, P_AS);
                cvt_tf32(a[r].x, a[r].num_elements);
            }
            #pragma unroll
            for (int j = 0; j < 4; j++) {
                TFragB b;
                wmma::load_matrix_sync(b, bc + (warp_n * 64 + 16 * j) * P_AS + kk, P_AS);
                cvt_tf32(b.x, b.num_elements);
                #pragma unroll
                for (int r = 0; r < 2; r++)
                    wmma::mma_sync(acc[r][j], a[r], b, acc[r][j]);
            }
        }
        __syncthreads();
    }

    // stage C, then bias + relu + bf16 scatter to (n,h,s,d)
    #pragma unroll
    for (int r = 0; r < 2; r++)
        #pragma unroll
        for (int j = 0; j < 4; j++)
            wmma::store_matrix_sync(
                Cs + (warp_m * 32 + 16 * r) * P_CS + warp_n * 64 + 16 * j,
                acc[r][j], P_CS, wmma::mem_row_major);
    __syncthreads();

    const int h = colBase >> 7;
    #pragma unroll
    for (int it = 0; it < 16; it++) {
        const int f   = tid + 256 * it;
        const int row = f >> 5;
        const int c4  = (f & 31) * 4;
        float4 v = *(const float4*)(Cs + row * P_CS + c4);
        const float4 bv = *(const float4*)(bias + colBase + c4);
        v.x = fmaxf(v.x + bv.x, 0.f);
        v.y = fmaxf(v.y + bv.y, 0.f);
        v.z = fmaxf(v.z + bv.z, 0.f);
        v.w = fmaxf(v.w + bv.w, 0.f);
        const int m  = rowBase + row;
        const int nb = m >> 11;
        const int s  = m & 2047;
        __nv_bfloat16* op = out + (((size_t)(nb * HEADS + h)) * SEQ + s) * HEAD_D + c4;
        *(__nv_bfloat162*)(op)     = __nv_bfloat162(__float2bfloat16(v.x), __float2bfloat16(v.y));
        *(__nv_bfloat162*)(op + 2) = __nv_bfloat162(__float2bfloat16(v.z), __float2bfloat16(v.w));
    }
}

// ---------------- attention (bf16 wmma, no-max softmax) -------------------------
#define BQ     64
#define BKV    64
#define QSTR   136   // bf16 row stride (halves): 272B = 17*16B, conflict-free
#define SF_STR 68    // fp32 S staging stride
#define P_STR  72    // bf16 P stride: 144B = 9*16B

__global__ __launch_bounds__(256, 2) void attn_kernel(
    const __nv_bfloat16* __restrict__ Q, const __nv_bfloat16* __restrict__ K,
    const __nv_bfloat16* __restrict__ V, const unsigned* __restrict__ mbits,
    float* __restrict__ out)
{
    extern __shared__ char smraw[];
    __nv_bfloat16* Qs = (__nv_bfloat16*)smraw;                 // 64 x QSTR
    __nv_bfloat16* Ks = Qs + BQ * QSTR;                        // 64 x QSTR
    __nv_bfloat16* Vs = Ks + BKV * QSTR;                       // 64 x QSTR
    float*         Sf = (float*)(Vs + BKV * QSTR);             // 64 x SF_STR
    __nv_bfloat16* Ps = (__nv_bfloat16*)(Sf + BQ * SF_STR);    // 64 x P_STR
    float*         Ls = (float*)(Ps + BQ * P_STR);             // 64

    const int tid    = threadIdx.x;
    const int warp   = tid >> 5;
    const int warp_m = warp >> 1;
    const int warp_n = warp & 1;
    const int n  = blockIdx.z;
    const int h  = blockIdx.y;
    const int qt = blockIdx.x;

    const __nv_bfloat16* Qg = Q + (((size_t)(n * HEADS + h)) * SEQ + qt * BQ) * HEAD_D;
    const __nv_bfloat16* Kg = K + (((size_t)(n * HEADS + h)) * SEQ) * HEAD_D;
    const __nv_bfloat16* Vg = V + (((size_t)(n * HEADS + h)) * SEQ) * HEAD_D;

    // load Q (64 x 128 bf16 = 1024 uint4)
    #pragma unroll
    for (int it = 0; it < 4; it++) {
        const int f   = tid + 256 * it;
        const int row = f >> 4;
        const int c8  = (f & 15) * 8;
        *(uint4*)(Qs + row * QSTR + c8) = *(const uint4*)(Qg + row * HEAD_D + c8);
    }
    if (tid < BQ) Ls[tid] = 0.f;

    BFragC oacc[4];
    #pragma unroll
    for (int j = 0; j < 4; j++) wmma::fill_fragment(oacc[j], 0.0f);

    const float scale = 0.08838834764831845f;   // 1/sqrt(128)
    const int q0 = qt * BQ;

    for (int kt = 0; kt < SEQ / BKV; kt++) {
        __syncthreads();   // prev PV done / Q load visible
        const __nv_bfloat16* Kt = Kg + (size_t)kt * BKV * HEAD_D;
        const __nv_bfloat16* Vt = Vg + (size_t)kt * BKV * HEAD_D;
        #pragma unroll
        for (int it = 0; it < 4; it++) {
            const int f   = tid + 256 * it;
            const int row = f >> 4;
            const int c8  = (f & 15) * 8;
            *(uint4*)(Ks + row * QSTR + c8) = *(const uint4*)(Kt + row * HEAD_D + c8);
            *(uint4*)(Vs + row * QSTR + c8) = *(const uint4*)(Vt + row * HEAD_D + c8);
        }
        __syncthreads();

        // S = Q @ K^T : warp -> 16 x 32
        BFragC sacc[2];
        wmma::fill_fragment(sacc[0], 0.0f);
        wmma::fill_fragment(sacc[1], 0.0f);
        #pragma unroll
        for (int d = 0; d < HEAD_D; d += 16) {
            BFragA a;
            wmma::load_matrix_sync(a, Qs + (warp_m * 16) * QSTR + d, QSTR);
            #pragma unroll
            for (int j = 0; j < 2; j++) {
                BFragBc b;
                wmma::load_matrix_sync(b, Ks + (warp_n * 32 + 16 * j) * QSTR + d, QSTR);
                wmma::mma_sync(sacc[j], a, b, sacc[j]);
            }
        }
        #pragma unroll
        for (int j = 0; j < 2; j++)
            wmma::store_matrix_sync(Sf + (warp_m * 16) * SF_STR + warp_n * 32 + 16 * j,
                                    sacc[j], SF_STR, wmma::mem_row_major);
        __syncthreads();

        // exp(scale*s) with mask bits; write bf16 P; accumulate L from rounded values
        {
            const int row = tid >> 2;
            const int seg = (tid & 3) * 16;
            const float* srow = Sf + row * SF_STR + seg;
            __nv_bfloat16* prow = Ps + row * P_STR + seg;
            const unsigned word =
                mbits[(size_t)(q0 + row) * (SEQ / 32) + kt * 2 + (seg >> 5)];
            const unsigned mseg = word >> (seg & 16);
            float psum = 0.f;
            #pragma unroll
            for (int c = 0; c < 16; c += 2) {
                float e0 = ((mseg >> (c + 0)) & 1u) ? __expf(srow[c + 0] * scale) : 0.f;
                float e1 = ((mseg >> (c + 1)) & 1u) ? __expf(srow[c + 1] * scale) : 0.f;
                const __nv_bfloat16 b0 = __float2bfloat16(e0);
                const __nv_bfloat16 b1 = __float2bfloat16(e1);
                *(__nv_bfloat162*)(prow + c) = __nv_bfloat162(b0, b1);
                psum += __bfloat162float(b0) + __bfloat162float(b1);
            }
            psum += __shfl_xor_sync(0xffffffffu, psum, 1);
            psum += __shfl_xor_sync(0xffffffffu, psum, 2);
            if ((tid & 3) == 0) Ls[row] += psum;
        }
        __syncthreads();

        // O += P @ V : warp -> rows warp_m*16, cols warp_n*64
        #pragma unroll
        for (int k = 0; k < BKV; k += 16) {
            BFragA a;
            wmma::load_matrix_sync(a, Ps + (warp_m * 16) * P_STR + k, P_STR);
            #pragma unroll
            for (int j = 0; j < 4; j++) {
                BFragBr b;
                wmma::load_matrix_sync(b, Vs + k * QSTR + warp_n * 64 + 16 * j, QSTR);
                wmma::mma_sync(oacc[j], a, b, oacc[j]);
            }
        }
    }
    __syncthreads();

    // stage O into Sf region (fp32, reuse Sf+Ps as 64 x 132 staging), normalize, write
    float* Os = Sf;   // 64 x 132 floats fits in Sf(64*68) + Ps-as-float(64*36) = 64*104... use Qs instead
    // Qs/Ks/Vs region = 3*64*136 bf16 = 52224B >= 64*132*4 = 33792B: stage O over Qs.
    Os = (float*)smraw;
    #pragma unroll
    for (int j = 0; j < 4; j++)
        wmma::store_matrix_sync(Os + (warp_m * 16) * 132 + warp_n * 64 + 16 * j,
                                oacc[j], 132, wmma::mem_row_major);
    __syncthreads();

    #pragma unroll
    for (int it = 0; it < 8; it++) {
        const int f   = tid + 256 * it;
        const int row = f >> 5;
        const int c4  = (f & 31) * 4;
        const float inv = 1.0f / Ls[row];
        float4 v = *(const float4*)(Os + row * 132 + c4);
        v.x *= inv; v.y *= inv; v.z *= inv; v.w *= inv;
        const int s = q0 + row;
        *(float4*)(out + ((size_t)n * SEQ + s) * OUTD + h * HEAD_D + c4) = v;
    }
}

// ---------------- launch --------------------------------------------------------
extern "C" void kernel_launch(void* const* d_in, const int* in_sizes, int n_in,
                              void* d_out, int out_size)
{
    const float* query = (const float*)d_in[0];
    const float* key   = (const float*)d_in[1];
    const float* value = (const float*)d_in[2];
    const int*   mask  = (const int*)d_in[3];
    const float* Wq    = (const float*)d_in[4];
    const float* bq    = (const float*)d_in[5];
    const float* Wk    = (const float*)d_in[6];
    const float* bk    = (const float*)d_in[7];
    const float* Wv    = (const float*)d_in[8];
    const float* bv    = (const float*)d_in[9];
    float* out = (float*)d_out;

    __nv_bfloat16 *qb, *kb, *vb;
    unsigned* mb;
    cudaGetSymbolAddress((void**)&qb, g_Q);
    cudaGetSymbolAddress((void**)&kb, g_K);
    cudaGetSymbolAddress((void**)&vb, g_V);
    cudaGetSymbolAddress((void**)&mb, g_mbits);

    pack_mask_kernel<<<(SEQ * SEQ) / 256, 256>>>(mask, mb);

    const int proj_smem = 4 * 128 * P_AS * sizeof(float);   // 73728
    cudaFuncSetAttribute(proj_kernel, cudaFuncAttributeMaxDynamicSharedMemorySize,
                         proj_smem);
    dim3 pgrid(OUTD / 128, M_TOTAL / 128);
    proj_kernel<<<pgrid, 256, proj_smem>>>(query, Wq, bq, qb);
    proj_kernel<<<pgrid, 256, proj_smem>>>(key,   Wk, bk, kb);
    proj_kernel<<<pgrid, 256, proj_smem>>>(value, Wv, bv, vb);

    const int attn_smem =
        (3 * BQ * QSTR) * 2 + (BQ * SF_STR) * 4 + (BQ * P_STR) * 2 + BQ * 4;  // 79104
    cudaFuncSetAttribute(attn_kernel, cudaFuncAttributeMaxDynamicSharedMemorySize,
                         attn_smem);
    dim3 agrid(SEQ / BQ, HEADS, NB);
    attn_kernel<<<agrid, 256, attn_smem>>>(qb, kb, vb, mb, out);
}

// round 5
// speedup vs baseline: 4.9807x; 1.8372x over previous
#include <cuda_runtime.h>
#include <cuda_bf16.h>
#include <mma.h>
#include <math.h>

using namespace nvcuda;

#define EMB     1024
#define HEADS   16
#define HEAD_D  128
#define NB      2
#define SEQ     2048
#define OUTD    (HEADS * HEAD_D)   // 2048
#define M_TOTAL (NB * SEQ)         // 4096
#define PK      EMB

// ---------------- scratch ------------------------------------------------------
__device__ __nv_bfloat16 g_Q[(size_t)NB * HEADS * SEQ * HEAD_D];
__device__ __nv_bfloat16 g_K[(size_t)NB * HEADS * SEQ * HEAD_D];
__device__ __nv_bfloat16 g_V[(size_t)NB * HEADS * SEQ * HEAD_D];
__device__ __nv_bfloat16 g_Xb[3][(size_t)M_TOTAL * PK];   // bf16 inputs
__device__ __nv_bfloat16 g_Wb[3][(size_t)OUTD * PK];      // bf16 weights
__device__ unsigned      g_mbits[SEQ * (SEQ / 32)];       // packed mask bits

// bf16 frags
typedef wmma::fragment<wmma::matrix_a, 16, 16, 16, __nv_bfloat16, wmma::row_major> BFragA;
typedef wmma::fragment<wmma::matrix_b, 16, 16, 16, __nv_bfloat16, wmma::col_major> BFragBc;
typedef wmma::fragment<wmma::matrix_b, 16, 16, 16, __nv_bfloat16, wmma::row_major> BFragBr;
typedef wmma::fragment<wmma::accumulator, 16, 16, 16, float> BFragC;

__device__ __forceinline__ void cp16(void* dst, const void* src) {
    unsigned d = (unsigned)__cvta_generic_to_shared(dst);
    asm volatile("cp.async.cg.shared.global [%0], [%1], 16;\n" :: "r"(d), "l"(src));
}
#define CP_COMMIT() asm volatile("cp.async.commit_group;\n" ::: "memory")
#define CP_WAIT(n)  asm volatile("cp.async.wait_group %0;\n" :: "n"(n) : "memory")

// ---------------- helpers ------------------------------------------------------
__global__ void pack_mask_kernel(const int* __restrict__ mask, unsigned* __restrict__ bits)
{
    const int e = blockIdx.x * 256 + threadIdx.x;
    const unsigned b = __ballot_sync(0xffffffffu, mask[e] != 0);
    if ((threadIdx.x & 31) == 0) bits[e >> 5] = b;
}

__global__ void cvt_bf16_kernel(const float* __restrict__ in,
                                __nv_bfloat16* __restrict__ out, int n4)
{
    for (int i = blockIdx.x * 256 + threadIdx.x; i < n4; i += gridDim.x * 256) {
        const float4 v = *(const float4*)(in + i * 4);
        __nv_bfloat16* o = out + i * 4;
        *(__nv_bfloat162*)(o)     = __nv_bfloat162(__float2bfloat16(v.x), __float2bfloat16(v.y));
        *(__nv_bfloat162*)(o + 2) = __nv_bfloat162(__float2bfloat16(v.z), __float2bfloat16(v.w));
    }
}

// ---------------- fused bf16 projections (grid.z selects q/k/v) -----------------
#define P_AS 40    // bf16 elems per smem row (80B, LDSM conflict-free)
#define P_CS 132   // fp32 epilogue staging stride

__global__ __launch_bounds__(256, 2) void proj_kernel(
    const __nv_bfloat16* __restrict__ X0, const __nv_bfloat16* __restrict__ X1,
    const __nv_bfloat16* __restrict__ X2,
    const __nv_bfloat16* __restrict__ W0, const __nv_bfloat16* __restrict__ W1,
    const __nv_bfloat16* __restrict__ W2,
    const float* __restrict__ b0, const float* __restrict__ b1,
    const float* __restrict__ b2,
    __nv_bfloat16* __restrict__ o0, __nv_bfloat16* __restrict__ o1,
    __nv_bfloat16* __restrict__ o2)
{
    const int z = blockIdx.z;
    const __nv_bfloat16* X = (z == 0) ? X0 : (z == 1) ? X1 : X2;
    const __nv_bfloat16* W = (z == 0) ? W0 : (z == 1) ? W1 : W2;
    const float*      bias = (z == 0) ? b0 : (z == 1) ? b1 : b2;
    __nv_bfloat16*     out = (z == 0) ? o0 : (z == 1) ? o1 : o2;

    extern __shared__ char smraw[];
    __nv_bfloat16* As[2] = { (__nv_bfloat16*)smraw,
                             (__nv_bfloat16*)smraw + 2 * 128 * P_AS };
    __nv_bfloat16* Bs[2] = { (__nv_bfloat16*)smraw + 128 * P_AS,
                             (__nv_bfloat16*)smraw + 3 * 128 * P_AS };
    float* Cs = (float*)smraw;

    const int tid    = threadIdx.x;
    const int warp   = tid >> 5;
    const int warp_m = warp >> 1;
    const int warp_n = warp & 1;
    const int rowBase = blockIdx.y * 128;
    const int colBase = blockIdx.x * 128;

    BFragC acc[2][4];
    #pragma unroll
    for (int i = 0; i < 2; i++)
        #pragma unroll
        for (int j = 0; j < 4; j++) wmma::fill_fragment(acc[i][j], 0.0f);

    const int NIT = PK / 32;   // 32

    // preload stage 0: A/B tiles are 128 rows x 32 bf16 = 128 x 4 chunks of 16B
    #pragma unroll
    for (int it = 0; it < 2; it++) {
        const int f = tid + 256 * it;          // 512 chunks
        const int row = f >> 2, c8 = (f & 3) * 8;
        cp16(As[0] + row * P_AS + c8, X + (size_t)(rowBase + row) * PK + c8);
        cp16(Bs[0] + row * P_AS + c8, W + (size_t)(colBase + row) * PK + c8);
    }
    CP_COMMIT();

    for (int i = 0; i < NIT; i++) {
        if (i + 1 < NIT) {
            const int k0 = (i + 1) * 32;
            __nv_bfloat16* an = As[(i + 1) & 1];
            __nv_bfloat16* bn = Bs[(i + 1) & 1];
            #pragma unroll
            for (int it = 0; it < 2; it++) {
                const int f = tid + 256 * it;
                const int row = f >> 2, c8 = (f & 3) * 8;
                cp16(an + row * P_AS + c8, X + (size_t)(rowBase + row) * PK + k0 + c8);
                cp16(bn + row * P_AS + c8, W + (size_t)(colBase + row) * PK + k0 + c8);
            }
            CP_COMMIT();
            CP_WAIT(1);
        } else {
            CP_WAIT(0);
        }
        __syncthreads();

        __nv_bfloat16* ac = As[i & 1];
        __nv_bfloat16* bc = Bs[i & 1];
        #pragma unroll
        for (int kk = 0; kk < 32; kk += 16) {
            BFragA a[2];
            #pragma unroll
            for (int r = 0; r < 2; r++)
                wmma::load_matrix_sync(a[r], ac + (warp_m * 32 + 16 * r) * P_AS + kk, P_AS);
            #pragma unroll
            for (int j = 0; j < 4; j++) {
                BFragBc b;
                wmma::load_matrix_sync(b, bc + (warp_n * 64 + 16 * j) * P_AS + kk, P_AS);
                #pragma unroll
                for (int r = 0; r < 2; r++)
                    wmma::mma_sync(acc[r][j], a[r], b, acc[r][j]);
            }
        }
        __syncthreads();
    }

    // epilogue: stage fp32 C, bias + relu, bf16 scatter to (n,h,s,d)
    #pragma unroll
    for (int r = 0; r < 2; r++)
        #pragma unroll
        for (int j = 0; j < 4; j++)
            wmma::store_matrix_sync(
                Cs + (warp_m * 32 + 16 * r) * P_CS + warp_n * 64 + 16 * j,
                acc[r][j], P_CS, wmma::mem_row_major);
    __syncthreads();

    const int h = colBase >> 7;
    #pragma unroll
    for (int it = 0; it < 16; it++) {
        const int f   = tid + 256 * it;
        const int row = f >> 5;
        const int c4  = (f & 31) * 4;
        float4 v = *(const float4*)(Cs + row * P_CS + c4);
        const float4 bv = *(const float4*)(bias + colBase + c4);
        v.x = fmaxf(v.x + bv.x, 0.f);
        v.y = fmaxf(v.y + bv.y, 0.f);
        v.z = fmaxf(v.z + bv.z, 0.f);
        v.w = fmaxf(v.w + bv.w, 0.f);
        const int m  = rowBase + row;
        const int nb = m >> 11;
        const int s  = m & 2047;
        __nv_bfloat16* op = out + (((size_t)(nb * HEADS + h)) * SEQ + s) * HEAD_D + c4;
        *(__nv_bfloat162*)(op)     = __nv_bfloat162(__float2bfloat16(v.x), __float2bfloat16(v.y));
        *(__nv_bfloat162*)(op + 2) = __nv_bfloat162(__float2bfloat16(v.z), __float2bfloat16(v.w));
    }
}

// ---------------- attention (bf16 wmma, no-max softmax) — unchanged from R4 -----
#define BQ     64
#define BKV    64
#define QSTR   136
#define SF_STR 68
#define P_STR  72

__global__ __launch_bounds__(256, 2) void attn_kernel(
    const __nv_bfloat16* __restrict__ Q, const __nv_bfloat16* __restrict__ K,
    const __nv_bfloat16* __restrict__ V, const unsigned* __restrict__ mbits,
    float* __restrict__ out)
{
    extern __shared__ char smraw[];
    __nv_bfloat16* Qs = (__nv_bfloat16*)smraw;
    __nv_bfloat16* Ks = Qs + BQ * QSTR;
    __nv_bfloat16* Vs = Ks + BKV * QSTR;
    float*         Sf = (float*)(Vs + BKV * QSTR);
    __nv_bfloat16* Ps = (__nv_bfloat16*)(Sf + BQ * SF_STR);
    float*         Ls = (float*)(Ps + BQ * P_STR);

    const int tid    = threadIdx.x;
    const int warp   = tid >> 5;
    const int warp_m = warp >> 1;
    const int warp_n = warp & 1;
    const int n  = blockIdx.z;
    const int h  = blockIdx.y;
    const int qt = blockIdx.x;

    const __nv_bfloat16* Qg = Q + (((size_t)(n * HEADS + h)) * SEQ + qt * BQ) * HEAD_D;
    const __nv_bfloat16* Kg = K + (((size_t)(n * HEADS + h)) * SEQ) * HEAD_D;
    const __nv_bfloat16* Vg = V + (((size_t)(n * HEADS + h)) * SEQ) * HEAD_D;

    #pragma unroll
    for (int it = 0; it < 4; it++) {
        const int f   = tid + 256 * it;
        const int row = f >> 4;
        const int c8  = (f & 15) * 8;
        *(uint4*)(Qs + row * QSTR + c8) = *(const uint4*)(Qg + row * HEAD_D + c8);
    }
    if (tid < BQ) Ls[tid] = 0.f;

    BFragC oacc[4];
    #pragma unroll
    for (int j = 0; j < 4; j++) wmma::fill_fragment(oacc[j], 0.0f);

    const float scale = 0.08838834764831845f;
    const int q0 = qt * BQ;

    for (int kt = 0; kt < SEQ / BKV; kt++) {
        __syncthreads();
        const __nv_bfloat16* Kt = Kg + (size_t)kt * BKV * HEAD_D;
        const __nv_bfloat16* Vt = Vg + (size_t)kt * BKV * HEAD_D;
        #pragma unroll
        for (int it = 0; it < 4; it++) {
            const int f   = tid + 256 * it;
            const int row = f >> 4;
            const int c8  = (f & 15) * 8;
            *(uint4*)(Ks + row * QSTR + c8) = *(const uint4*)(Kt + row * HEAD_D + c8);
            *(uint4*)(Vs + row * QSTR + c8) = *(const uint4*)(Vt + row * HEAD_D + c8);
        }
        __syncthreads();

        BFragC sacc[2];
        wmma::fill_fragment(sacc[0], 0.0f);
        wmma::fill_fragment(sacc[1], 0.0f);
        #pragma unroll
        for (int d = 0; d < HEAD_D; d += 16) {
            BFragA a;
            wmma::load_matrix_sync(a, Qs + (warp_m * 16) * QSTR + d, QSTR);
            #pragma unroll
            for (int j = 0; j < 2; j++) {
                BFragBc b;
                wmma::load_matrix_sync(b, Ks + (warp_n * 32 + 16 * j) * QSTR + d, QSTR);
                wmma::mma_sync(sacc[j], a, b, sacc[j]);
            }
        }
        #pragma unroll
        for (int j = 0; j < 2; j++)
            wmma::store_matrix_sync(Sf + (warp_m * 16) * SF_STR + warp_n * 32 + 16 * j,
                                    sacc[j], SF_STR, wmma::mem_row_major);
        __syncthreads();

        {
            const int row = tid >> 2;
            const int seg = (tid & 3) * 16;
            const float* srow = Sf + row * SF_STR + seg;
            __nv_bfloat16* prow = Ps + row * P_STR + seg;
            const unsigned word =
                mbits[(size_t)(q0 + row) * (SEQ / 32) + kt * 2 + (seg >> 5)];
            const unsigned mseg = word >> (seg & 16);
            float psum = 0.f;
            #pragma unroll
            for (int c = 0; c < 16; c += 2) {
                float e0 = ((mseg >> (c + 0)) & 1u) ? __expf(srow[c + 0] * scale) : 0.f;
                float e1 = ((mseg >> (c + 1)) & 1u) ? __expf(srow[c + 1] * scale) : 0.f;
                const __nv_bfloat16 bb0 = __float2bfloat16(e0);
                const __nv_bfloat16 bb1 = __float2bfloat16(e1);
                *(__nv_bfloat162*)(prow + c) = __nv_bfloat162(bb0, bb1);
                psum += __bfloat162float(bb0) + __bfloat162float(bb1);
            }
            psum += __shfl_xor_sync(0xffffffffu, psum, 1);
            psum += __shfl_xor_sync(0xffffffffu, psum, 2);
            if ((tid & 3) == 0) Ls[row] += psum;
        }
        __syncthreads();

        #pragma unroll
        for (int k = 0; k < BKV; k += 16) {
            BFragA a;
            wmma::load_matrix_sync(a, Ps + (warp_m * 16) * P_STR + k, P_STR);
            #pragma unroll
            for (int j = 0; j < 4; j++) {
                BFragBr b;
                wmma::load_matrix_sync(b, Vs + k * QSTR + warp_n * 64 + 16 * j, QSTR);
                wmma::mma_sync(oacc[j], a, b, oacc[j]);
            }
        }
    }
    __syncthreads();

    float* Os = (float*)smraw;
    #pragma unroll
    for (int j = 0; j < 4; j++)
        wmma::store_matrix_sync(Os + (warp_m * 16) * 132 + warp_n * 64 + 16 * j,
                                oacc[j], 132, wmma::mem_row_major);
    __syncthreads();

    #pragma unroll
    for (int it = 0; it < 8; it++) {
        const int f   = tid + 256 * it;
        const int row = f >> 5;
        const int c4  = (f & 31) * 4;
        const float inv = 1.0f / Ls[row];
        float4 v = *(const float4*)(Os + row * 132 + c4);
        v.x *= inv; v.y *= inv; v.z *= inv; v.w *= inv;
        const int s = q0 + row;
        *(float4*)(out + ((size_t)n * SEQ + s) * OUTD + h * HEAD_D + c4) = v;
    }
}

// ---------------- launch --------------------------------------------------------
extern "C" void kernel_launch(void* const* d_in, const int* in_sizes, int n_in,
                              void* d_out, int out_size)
{
    const float* query = (const float*)d_in[0];
    const float* key   = (const float*)d_in[1];
    const float* value = (const float*)d_in[2];
    const int*   mask  = (const int*)d_in[3];
    const float* Wq    = (const float*)d_in[4];
    const float* bq    = (const float*)d_in[5];
    const float* Wk    = (const float*)d_in[6];
    const float* bk    = (const float*)d_in[7];
    const float* Wv    = (const float*)d_in[8];
    const float* bv    = (const float*)d_in[9];
    float* out = (float*)d_out;

    __nv_bfloat16 *qb, *kb, *vb, *xb, *wb;
    unsigned* mb;
    cudaGetSymbolAddress((void**)&qb, g_Q);
    cudaGetSymbolAddress((void**)&kb, g_K);
    cudaGetSymbolAddress((void**)&vb, g_V);
    cudaGetSymbolAddress((void**)&xb, g_Xb);
    cudaGetSymbolAddress((void**)&wb, g_Wb);
    cudaGetSymbolAddress((void**)&mb, g_mbits);

    const size_t XN = (size_t)M_TOTAL * PK;   // 4M elems
    const size_t WN = (size_t)OUTD * PK;      // 2M elems
    __nv_bfloat16* Xb0 = xb;
    __nv_bfloat16* Xb1 = xb + XN;
    __nv_bfloat16* Xb2 = xb + 2 * XN;
    __nv_bfloat16* Wb0 = wb;
    __nv_bfloat16* Wb1 = wb + WN;
    __nv_bfloat16* Wb2 = wb + 2 * WN;

    cvt_bf16_kernel<<<2048, 256>>>(query, Xb0, (int)(XN / 4));
    cvt_bf16_kernel<<<2048, 256>>>(key,   Xb1, (int)(XN / 4));
    cvt_bf16_kernel<<<2048, 256>>>(value, Xb2, (int)(XN / 4));
    cvt_bf16_kernel<<<1024, 256>>>(Wq,    Wb0, (int)(WN / 4));
    cvt_bf16_kernel<<<1024, 256>>>(Wk,    Wb1, (int)(WN / 4));
    cvt_bf16_kernel<<<1024, 256>>>(Wv,    Wb2, (int)(WN / 4));
    pack_mask_kernel<<<(SEQ * SEQ) / 256, 256>>>(mask, mb);

    const int proj_smem = 128 * P_CS * sizeof(float);   // 67584 (>= 4*128*P_AS*2 = 40960)
    cudaFuncSetAttribute(proj_kernel, cudaFuncAttributeMaxDynamicSharedMemorySize,
                         proj_smem);
    dim3 pgrid(OUTD / 128, M_TOTAL / 128, 3);
    proj_kernel<<<pgrid, 256, proj_smem>>>(Xb0, Xb1, Xb2, Wb0, Wb1, Wb2,
                                           bq, bk, bv, qb, kb, vb);

    const int attn_smem =
        (3 * BQ * QSTR) * 2 + (BQ * SF_STR) * 4 + (BQ * P_STR) * 2 + BQ * 4;
    cudaFuncSetAttribute(attn_kernel, cudaFuncAttributeMaxDynamicSharedMemorySize,
                         attn_smem);
    dim3 agrid(SEQ / BQ, HEADS, NB);
    attn_kernel<<<agrid, 256, attn_smem>>>(qb, kb, vb, mb, out);
}

// round 7
// speedup vs baseline: 6.6451x; 1.3342x over previous
#include <cuda_runtime.h>
#include <cuda_bf16.h>
#include <mma.h>
#include <cstdint>
#include <math.h>

using namespace nvcuda;

#define EMB     1024
#define HEADS   16
#define HEAD_D  128
#define NB      2
#define SEQ     2048
#define OUTD    (HEADS * HEAD_D)   // 2048
#define M_TOTAL (NB * SEQ)         // 4096
#define PK      EMB

// ---------------- scratch ------------------------------------------------------
__device__ __nv_bfloat16 g_Q[(size_t)NB * HEADS * SEQ * HEAD_D];
__device__ __nv_bfloat16 g_K[(size_t)NB * HEADS * SEQ * HEAD_D];
__device__ __nv_bfloat16 g_V[(size_t)NB * HEADS * SEQ * HEAD_D];
__device__ __nv_bfloat16 g_Xb[(size_t)3 * M_TOTAL * PK];
__device__ __nv_bfloat16 g_Wb[(size_t)3 * OUTD * PK];
__device__ unsigned      g_mbits[SEQ * (SEQ / 32)];

// bf16 wmma frags (projection)
typedef wmma::fragment<wmma::matrix_a, 16, 16, 16, __nv_bfloat16, wmma::row_major> BFragA;
typedef wmma::fragment<wmma::matrix_b, 16, 16, 16, __nv_bfloat16, wmma::col_major> BFragBc;
typedef wmma::fragment<wmma::accumulator, 16, 16, 16, float> BFragC;

__device__ __forceinline__ void cp16(void* dst, const void* src) {
    unsigned d = (unsigned)__cvta_generic_to_shared(dst);
    asm volatile("cp.async.cg.shared.global [%0], [%1], 16;\n" :: "r"(d), "l"(src));
}
#define CP_COMMIT() asm volatile("cp.async.commit_group;\n" ::: "memory")
#define CP_WAIT(k)  asm volatile("cp.async.wait_group %0;\n" :: "n"(k) : "memory")

__device__ __forceinline__ void ldsm_x4(unsigned* r, unsigned addr) {
    asm volatile("ldmatrix.sync.aligned.m8n8.x4.shared.b16 {%0,%1,%2,%3}, [%4];"
        : "=r"(r[0]), "=r"(r[1]), "=r"(r[2]), "=r"(r[3]) : "r"(addr));
}
__device__ __forceinline__ void ldsm_x4t(unsigned* r, unsigned addr) {
    asm volatile("ldmatrix.sync.aligned.m8n8.x4.trans.shared.b16 {%0,%1,%2,%3}, [%4];"
        : "=r"(r[0]), "=r"(r[1]), "=r"(r[2]), "=r"(r[3]) : "r"(addr));
}
__device__ __forceinline__ void mma16816(float* c, const unsigned* a,
                                         unsigned b0, unsigned b1) {
    asm volatile(
        "mma.sync.aligned.m16n8k16.row.col.f32.bf16.bf16.f32 "
        "{%0,%1,%2,%3}, {%4,%5,%6,%7}, {%8,%9}, {%0,%1,%2,%3};"
        : "+f"(c[0]), "+f"(c[1]), "+f"(c[2]), "+f"(c[3])
        : "r"(a[0]), "r"(a[1]), "r"(a[2]), "r"(a[3]), "r"(b0), "r"(b1));
}
__device__ __forceinline__ unsigned packbf(float lo, float hi) {
    unsigned d;
    asm("cvt.rn.bf16x2.f32 %0, %1, %2;" : "=r"(d) : "f"(hi), "f"(lo));
    return d;
}

// ---------------- helpers ------------------------------------------------------
__global__ void pack_mask_kernel(const int* __restrict__ mask, unsigned* __restrict__ bits)
{
    const int e = blockIdx.x * 256 + threadIdx.x;
    const unsigned b = __ballot_sync(0xffffffffu, mask[e] != 0);
    if ((threadIdx.x & 31) == 0) bits[e >> 5] = b;
}

__global__ void cvt_bf16_kernel(const float* __restrict__ in,
                                __nv_bfloat16* __restrict__ out, int n4)
{
    for (int i = blockIdx.x * 256 + threadIdx.x; i < n4; i += gridDim.x * 256) {
        const float4 v = *(const float4*)(in + i * 4);
        __nv_bfloat16* o = out + i * 4;
        *(__nv_bfloat162*)(o)     = __nv_bfloat162(__float2bfloat16(v.x), __float2bfloat16(v.y));
        *(__nv_bfloat162*)(o + 2) = __nv_bfloat162(__float2bfloat16(v.z), __float2bfloat16(v.w));
    }
}

// ---------------- fused bf16 projections (grid.z selects q/k/v) -----------------
#define P_AS 40
#define P_CS 132

__global__ __launch_bounds__(256, 2) void proj_kernel(
    const __nv_bfloat16* __restrict__ X0, const __nv_bfloat16* __restrict__ X1,
    const __nv_bfloat16* __restrict__ X2,
    const __nv_bfloat16* __restrict__ W0, const __nv_bfloat16* __restrict__ W1,
    const __nv_bfloat16* __restrict__ W2,
    const float* __restrict__ b0, const float* __restrict__ b1,
    const float* __restrict__ b2,
    __nv_bfloat16* __restrict__ o0, __nv_bfloat16* __restrict__ o1,
    __nv_bfloat16* __restrict__ o2)
{
    const int z = blockIdx.z;
    const __nv_bfloat16* X = (z == 0) ? X0 : (z == 1) ? X1 : X2;
    const __nv_bfloat16* W = (z == 0) ? W0 : (z == 1) ? W1 : W2;
    const float*      bias = (z == 0) ? b0 : (z == 1) ? b1 : b2;
    __nv_bfloat16*     out = (z == 0) ? o0 : (z == 1) ? o1 : o2;

    extern __shared__ char smraw[];
    __nv_bfloat16* As[2];
    __nv_bfloat16* Bs[2];
    As[0] = (__nv_bfloat16*)smraw;
    Bs[0] = As[0] + 128 * P_AS;
    As[1] = As[0] + 2 * 128 * P_AS;
    Bs[1] = As[0] + 3 * 128 * P_AS;
    float* Cs = (float*)smraw;

    const int tid    = threadIdx.x;
    const int warp   = tid >> 5;
    const int warp_m = warp >> 1;
    const int warp_n = warp & 1;
    const int rowBase = blockIdx.y * 128;
    const int colBase = blockIdx.x * 128;

    BFragC acc[2][4];
    #pragma unroll
    for (int i = 0; i < 2; i++)
        #pragma unroll
        for (int j = 0; j < 4; j++) wmma::fill_fragment(acc[i][j], 0.0f);

    const int NIT = PK / 32;

    #pragma unroll
    for (int it = 0; it < 2; it++) {
        const int f = tid + 256 * it;
        const int row = f >> 2;
        const int c8 = (f & 3) * 8;
        cp16(As[0] + row * P_AS + c8, X + (size_t)(rowBase + row) * PK + c8);
        cp16(Bs[0] + row * P_AS + c8, W + (size_t)(colBase + row) * PK + c8);
    }
    CP_COMMIT();

    for (int i = 0; i < NIT; i++) {
        if (i + 1 < NIT) {
            const int k0 = (i + 1) * 32;
            __nv_bfloat16* an = As[(i + 1) & 1];
            __nv_bfloat16* bn = Bs[(i + 1) & 1];
            #pragma unroll
            for (int it = 0; it < 2; it++) {
                const int f = tid + 256 * it;
                const int row = f >> 2;
                const int c8 = (f & 3) * 8;
                cp16(an + row * P_AS + c8, X + (size_t)(rowBase + row) * PK + k0 + c8);
                cp16(bn + row * P_AS + c8, W + (size_t)(colBase + row) * PK + k0 + c8);
            }
            CP_COMMIT();
            CP_WAIT(1);
        } else {
            CP_WAIT(0);
        }
        __syncthreads();

        __nv_bfloat16* ac = As[i & 1];
        __nv_bfloat16* bc = Bs[i & 1];
        #pragma unroll
        for (int kk = 0; kk < 32; kk += 16) {
            BFragA a[2];
            #pragma unroll
            for (int r = 0; r < 2; r++)
                wmma::load_matrix_sync(a[r], ac + (warp_m * 32 + 16 * r) * P_AS + kk, P_AS);
            #pragma unroll
            for (int j = 0; j < 4; j++) {
                BFragBc b;
                wmma::load_matrix_sync(b, bc + (warp_n * 64 + 16 * j) * P_AS + kk, P_AS);
                #pragma unroll
                for (int r = 0; r < 2; r++)
                    wmma::mma_sync(acc[r][j], a[r], b, acc[r][j]);
            }
        }
        __syncthreads();
    }

    #pragma unroll
    for (int r = 0; r < 2; r++)
        #pragma unroll
        for (int j = 0; j < 4; j++)
            wmma::store_matrix_sync(
                Cs + (warp_m * 32 + 16 * r) * P_CS + warp_n * 64 + 16 * j,
                acc[r][j], P_CS, wmma::mem_row_major);
    __syncthreads();

    const int h = colBase >> 7;
    #pragma unroll
    for (int it = 0; it < 16; it++) {
        const int f   = tid + 256 * it;
        const int row = f >> 5;
        const int c4  = (f & 31) * 4;
        float4 v = *(const float4*)(Cs + row * P_CS + c4);
        const float4 bv = *(const float4*)(bias + colBase + c4);
        v.x = fmaxf(v.x + bv.x, 0.f);
        v.y = fmaxf(v.y + bv.y, 0.f);
        v.z = fmaxf(v.z + bv.z, 0.f);
        v.w = fmaxf(v.w + bv.w, 0.f);
        const int m  = rowBase + row;
        const int nb = m >> 11;
        const int s  = m & 2047;
        __nv_bfloat16* op = out + (((size_t)(nb * HEADS + h)) * SEQ + s) * HEAD_D + c4;
        *(__nv_bfloat162*)(op)     = __nv_bfloat162(__float2bfloat16(v.x), __float2bfloat16(v.y));
        *(__nv_bfloat162*)(op + 2) = __nv_bfloat162(__float2bfloat16(v.z), __float2bfloat16(v.w));
    }
}

// ---------------- attention: register-resident FA2-style, raw mma --------------
#define BQ    128
#define BKV   64
#define QSTR  136          // bf16 row stride: 272B, ldmatrix conflict-free
#define NT    (SEQ / BKV)  // 32
#define OSTR  132

__global__ __launch_bounds__(256, 1) void attn_kernel(
    const __nv_bfloat16* __restrict__ Q, const __nv_bfloat16* __restrict__ K,
    const __nv_bfloat16* __restrict__ V, const unsigned* __restrict__ mbits,
    float* __restrict__ out)
{
    extern __shared__ char smraw[];
    __nv_bfloat16* Qs  = (__nv_bfloat16*)smraw;      // 128 x QSTR
    __nv_bfloat16* KV0 = Qs + BQ * QSTR;             // 2 stages x (K 64xQSTR, V 64xQSTR)
    float*         Os  = (float*)KV0;                // epilogue staging

    const int tid  = threadIdx.x;
    const int warp = tid >> 5;
    const int lane = tid & 31;
    const int nb = blockIdx.z;
    const int h  = blockIdx.y;
    const int qt = blockIdx.x;
    const int q0 = qt * BQ;

    const __nv_bfloat16* Qg = Q + (((size_t)(nb * HEADS + h)) * SEQ + q0) * HEAD_D;
    const __nv_bfloat16* Kg = K + (((size_t)(nb * HEADS + h)) * SEQ) * HEAD_D;
    const __nv_bfloat16* Vg = V + (((size_t)(nb * HEADS + h)) * SEQ) * HEAD_D;

    // async load Q (group 0)
    #pragma unroll
    for (int it = 0; it < 8; it++) {
        const int f = tid + 256 * it;
        const int row = f >> 4;
        const int c8 = (f & 15) * 8;
        cp16(Qs + row * QSTR + c8, Qg + row * HEAD_D + c8);
    }
    CP_COMMIT();

    // async load K/V stage 0 (group 1)
    {
        __nv_bfloat16* Ks0 = KV0;
        __nv_bfloat16* Vs0 = KV0 + BKV * QSTR;
        #pragma unroll
        for (int it = 0; it < 4; it++) {
            const int f = tid + 256 * it;
            const int row = f >> 4;
            const int c8 = (f & 15) * 8;
            cp16(Ks0 + row * QSTR + c8, Kg + row * HEAD_D + c8);
            cp16(Vs0 + row * QSTR + c8, Vg + row * HEAD_D + c8);
        }
    }
    CP_COMMIT();

    CP_WAIT(1);          // Q arrived
    __syncthreads();

    // persistent Q A-fragments
    const unsigned qbase = (unsigned)__cvta_generic_to_shared(Qs);
    unsigned qa[8][4];
    {
        const int qrow = warp * 16 + (lane & 15);
        const int qco  = (lane >> 4) << 3;
        #pragma unroll
        for (int d8 = 0; d8 < 8; d8++)
            ldsm_x4(qa[d8], qbase + (unsigned)((qrow * QSTR + d8 * 16 + qco) * 2));
    }

    float oacc[16][4];
    #pragma unroll
    for (int j = 0; j < 16; j++) {
        #pragma unroll
        for (int c = 0; c < 4; c++) oacc[j][c] = 0.f;
    }
    float li0 = 0.f;
    float li1 = 0.f;

    const float scale = 0.08838834764831845f;   // 1/sqrt(128)
    const int lq2 = (lane & 3) * 2;
    const int r0  = lane >> 2;
    const unsigned* mrow0 = mbits + (size_t)(q0 + warp * 16 + r0) * (SEQ / 32);
    const unsigned* mrow1 = mrow0 + 8 * (SEQ / 32);

    const int krow_off = (lane & 7) + ((lane >> 4) << 3);
    const int kcol_off = lane & 8;
    const int vrow_off = lane & 15;
    const int vcol_off = (lane >> 4) << 3;

    for (int kt = 0; kt < NT; kt++) {
        const int st = kt & 1;
        __syncthreads();   // everyone done reading stage st^1
        if (kt + 1 < NT) {
            __nv_bfloat16* Kn = KV0 + (st ^ 1) * 2 * BKV * QSTR;
            __nv_bfloat16* Vn = Kn + BKV * QSTR;
            const __nv_bfloat16* Kt = Kg + (size_t)(kt + 1) * BKV * HEAD_D;
            const __nv_bfloat16* Vt = Vg + (size_t)(kt + 1) * BKV * HEAD_D;
            #pragma unroll
            for (int it = 0; it < 4; it++) {
                const int f = tid + 256 * it;
                const int row = f >> 4;
                const int c8 = (f & 15) * 8;
                cp16(Kn + row * QSTR + c8, Kt + row * HEAD_D + c8);
                cp16(Vn + row * QSTR + c8, Vt + row * HEAD_D + c8);
            }
            CP_COMMIT();
            CP_WAIT(1);
        } else {
            CP_WAIT(0);
        }
        __syncthreads();   // stage st visible

        __nv_bfloat16* Ks = KV0 + st * 2 * BKV * QSTR;
        __nv_bfloat16* Vs = Ks + BKV * QSTR;
        const unsigned kbase = (unsigned)__cvta_generic_to_shared(Ks);
        const unsigned vbase = (unsigned)__cvta_generic_to_shared(Vs);

        // S = Q @ K^T (16 x 64 per warp), registers only
        float sacc[8][4];
        #pragma unroll
        for (int j = 0; j < 8; j++) {
            #pragma unroll
            for (int c = 0; c < 4; c++) sacc[j][c] = 0.f;
        }

        #pragma unroll
        for (int d8 = 0; d8 < 8; d8++) {
            #pragma unroll
            for (int jp = 0; jp < 4; jp++) {
                unsigned b[4];
                ldsm_x4(b, kbase + (unsigned)(((jp * 16 + krow_off) * QSTR
                                               + d8 * 16 + kcol_off) * 2));
                mma16816(sacc[2 * jp],     qa[d8], b[0], b[1]);
                mma16816(sacc[2 * jp + 1], qa[d8], b[2], b[3]);
            }
        }

        // mask + exp in registers; accumulate partial row sums
        const unsigned w00 = mrow0[kt * 2];
        const unsigned w01 = mrow0[kt * 2 + 1];
        const unsigned w10 = mrow1[kt * 2];
        const unsigned w11 = mrow1[kt * 2 + 1];
        #pragma unroll
        for (int j = 0; j < 8; j++) {
            const int sh = (j * 8 + lq2) & 31;
            const unsigned wa = (j < 4) ? w00 : w01;
            const unsigned wb = (j < 4) ? w10 : w11;
            const float e0 = ((wa >> sh) & 1u)       ? __expf(sacc[j][0] * scale) : 0.f;
            const float e1 = ((wa >> (sh + 1)) & 1u) ? __expf(sacc[j][1] * scale) : 0.f;
            const float e2 = ((wb >> sh) & 1u)       ? __expf(sacc[j][2] * scale) : 0.f;
            const float e3 = ((wb >> (sh + 1)) & 1u) ? __expf(sacc[j][3] * scale) : 0.f;
            sacc[j][0] = e0;
            sacc[j][1] = e1;
            sacc[j][2] = e2;
            sacc[j][3] = e3;
            li0 += e0 + e1;
            li1 += e2 + e3;
        }

        // O += P @ V (P repacked in registers as A-fragments)
        #pragma unroll
        for (int kk = 0; kk < 4; kk++) {
            unsigned pa[4];
            pa[0] = packbf(sacc[2 * kk][0],     sacc[2 * kk][1]);
            pa[1] = packbf(sacc[2 * kk][2],     sacc[2 * kk][3]);
            pa[2] = packbf(sacc[2 * kk + 1][0], sacc[2 * kk + 1][1]);
            pa[3] = packbf(sacc[2 * kk + 1][2], sacc[2 * kk + 1][3]);
            #pragma unroll
            for (int dp = 0; dp < 8; dp++) {
                unsigned v[4];
                ldsm_x4t(v, vbase + (unsigned)(((kk * 16 + vrow_off) * QSTR
                                                + dp * 16 + vcol_off) * 2));
                mma16816(oacc[2 * dp],     pa, v[0], v[1]);
                mma16816(oacc[2 * dp + 1], pa, v[2], v[3]);
            }
        }
    }

    __syncthreads();   // all warps done with KV smem before O staging overwrites it

    // reduce row sums across the quad (cols are spread over lanes with same r0)
    li0 += __shfl_xor_sync(0xffffffffu, li0, 1);
    li0 += __shfl_xor_sync(0xffffffffu, li0, 2);
    li1 += __shfl_xor_sync(0xffffffffu, li1, 1);
    li1 += __shfl_xor_sync(0xffffffffu, li1, 2);
    const float inv0 = 1.0f / li0;
    const float inv1 = 1.0f / li1;

    // normalize + stage to smem, coalesced write
    {
        float* o0 = Os + (warp * 16 + r0) * OSTR + lq2;
        float* o1 = o0 + 8 * OSTR;
        #pragma unroll
        for (int dj = 0; dj < 16; dj++) {
            o0[dj * 8 + 0] = oacc[dj][0] * inv0;
            o0[dj * 8 + 1] = oacc[dj][1] * inv0;
            o1[dj * 8 + 0] = oacc[dj][2] * inv1;
            o1[dj * 8 + 1] = oacc[dj][3] * inv1;
        }
    }
    __syncthreads();

    #pragma unroll
    for (int it = 0; it < 16; it++) {
        const int f   = tid + 256 * it;
        const int row = f >> 5;
        const int c4  = (f & 31) * 4;
        const float4 v = *(const float4*)(Os + row * OSTR + c4);
        const int s = q0 + row;
        *(float4*)(out + ((size_t)nb * SEQ + s) * OUTD + h * HEAD_D + c4) = v;
    }
}

// ---------------- launch --------------------------------------------------------
extern "C" void kernel_launch(void* const* d_in, const int* in_sizes, int n_in,
                              void* d_out, int out_size)
{
    const float* query = (const float*)d_in[0];
    const float* key   = (const float*)d_in[1];
    const float* value = (const float*)d_in[2];
    const int*   mask  = (const int*)d_in[3];
    const float* Wq    = (const float*)d_in[4];
    const float* bq    = (const float*)d_in[5];
    const float* Wk    = (const float*)d_in[6];
    const float* bk    = (const float*)d_in[7];
    const float* Wv    = (const float*)d_in[8];
    const float* bv    = (const float*)d_in[9];
    float* out = (float*)d_out;

    __nv_bfloat16 *qb = 0, *kb = 0, *vb = 0, *xb = 0, *wb = 0;
    unsigned* mb = 0;
    cudaGetSymbolAddress((void**)&qb, g_Q);
    cudaGetSymbolAddress((void**)&kb, g_K);
    cudaGetSymbolAddress((void**)&vb, g_V);
    cudaGetSymbolAddress((void**)&xb, g_Xb);
    cudaGetSymbolAddress((void**)&wb, g_Wb);
    cudaGetSymbolAddress((void**)&mb, g_mbits);

    const size_t XN = (size_t)M_TOTAL * PK;
    const size_t WN = (size_t)OUTD * PK;
    __nv_bfloat16* Xb0 = xb;
    __nv_bfloat16* Xb1 = xb + XN;
    __nv_bfloat16* Xb2 = xb + 2 * XN;
    __nv_bfloat16* Wb0 = wb;
    __nv_bfloat16* Wb1 = wb + WN;
    __nv_bfloat16* Wb2 = wb + 2 * WN;

    cvt_bf16_kernel<<<2048, 256>>>(query, Xb0, (int)(XN / 4));
    cvt_bf16_kernel<<<2048, 256>>>(key,   Xb1, (int)(XN / 4));
    cvt_bf16_kernel<<<2048, 256>>>(value, Xb2, (int)(XN / 4));
    cvt_bf16_kernel<<<1024, 256>>>(Wq,    Wb0, (int)(WN / 4));
    cvt_bf16_kernel<<<1024, 256>>>(Wk,    Wb1, (int)(WN / 4));
    cvt_bf16_kernel<<<1024, 256>>>(Wv,    Wb2, (int)(WN / 4));
    pack_mask_kernel<<<(SEQ * SEQ) / 256, 256>>>(mask, mb);

    const int proj_smem = 128 * P_CS * (int)sizeof(float);
    cudaFuncSetAttribute(proj_kernel, cudaFuncAttributeMaxDynamicSharedMemorySize,
                         proj_smem);
    dim3 pgrid(OUTD / 128, M_TOTAL / 128, 3);
    proj_kernel<<<pgrid, 256, proj_smem>>>(Xb0, Xb1, Xb2, Wb0, Wb1, Wb2,
                                           bq, bk, bv, qb, kb, vb);

    const int attn_smem = (BQ * QSTR + 4 * BKV * QSTR) * 2;   // 104448
    cudaFuncSetAttribute(attn_kernel, cudaFuncAttributeMaxDynamicSharedMemorySize,
                         attn_smem);
    dim3 agrid(SEQ / BQ, HEADS, NB);
    attn_kernel<<<agrid, 256, attn_smem>>>(qb, kb, vb, mb, out);
}

// round 9
// speedup vs baseline: 8.0847x; 1.2166x over previous
#include <cuda_runtime.h>
#include <cuda_bf16.h>
#include <cstdint>
#include <math.h>

#define EMB     1024
#define HEADS   16
#define HEAD_D  128
#define NB      2
#define SEQ     2048
#define OUTD    (HEADS * HEAD_D)   // 2048
#define M_TOTAL (NB * SEQ)         // 4096
#define PK      EMB

// ---------------- scratch ------------------------------------------------------
__device__ __nv_bfloat16 g_Q[(size_t)NB * HEADS * SEQ * HEAD_D];
__device__ __nv_bfloat16 g_K[(size_t)NB * HEADS * SEQ * HEAD_D];
__device__ __nv_bfloat16 g_V[(size_t)NB * HEADS * SEQ * HEAD_D];
__device__ __nv_bfloat16 g_Xb[(size_t)3 * M_TOTAL * PK];
__device__ __nv_bfloat16 g_Wb[(size_t)3 * OUTD * PK];
__device__ unsigned      g_mbits[SEQ * (SEQ / 32)];

__device__ __forceinline__ void cp16(void* dst, const void* src) {
    unsigned d = (unsigned)__cvta_generic_to_shared(dst);
    asm volatile("cp.async.cg.shared.global [%0], [%1], 16;\n" :: "r"(d), "l"(src));
}
__device__ __forceinline__ void cp16s(unsigned dst, const void* src) {
    asm volatile("cp.async.cg.shared.global [%0], [%1], 16;\n" :: "r"(dst), "l"(src));
}
#define CP_COMMIT() asm volatile("cp.async.commit_group;\n" ::: "memory")
#define CP_WAIT(k)  asm volatile("cp.async.wait_group %0;\n" :: "n"(k) : "memory")

__device__ __forceinline__ void ldsm_x4(unsigned* r, unsigned addr) {
    asm volatile("ldmatrix.sync.aligned.m8n8.x4.shared.b16 {%0,%1,%2,%3}, [%4];"
        : "=r"(r[0]), "=r"(r[1]), "=r"(r[2]), "=r"(r[3]) : "r"(addr));
}
__device__ __forceinline__ void ldsm_x4t(unsigned* r, unsigned addr) {
    asm volatile("ldmatrix.sync.aligned.m8n8.x4.trans.shared.b16 {%0,%1,%2,%3}, [%4];"
        : "=r"(r[0]), "=r"(r[1]), "=r"(r[2]), "=r"(r[3]) : "r"(addr));
}
__device__ __forceinline__ void mma16816(float* c, const unsigned* a,
                                         unsigned b0, unsigned b1) {
    asm volatile(
        "mma.sync.aligned.m16n8k16.row.col.f32.bf16.bf16.f32 "
        "{%0,%1,%2,%3}, {%4,%5,%6,%7}, {%8,%9}, {%0,%1,%2,%3};"
        : "+f"(c[0]), "+f"(c[1]), "+f"(c[2]), "+f"(c[3])
        : "r"(a[0]), "r"(a[1]), "r"(a[2]), "r"(a[3]), "r"(b0), "r"(b1));
}
__device__ __forceinline__ unsigned packbf(float lo, float hi) {
    unsigned d;
    asm("cvt.rn.bf16x2.f32 %0, %1, %2;" : "=r"(d) : "f"(hi), "f"(lo));
    return d;
}

// ---------------- helpers ------------------------------------------------------
__global__ void pack_mask_kernel(const int* __restrict__ mask, unsigned* __restrict__ bits)
{
    const int e = blockIdx.x * 256 + threadIdx.x;
    const unsigned b = __ballot_sync(0xffffffffu, mask[e] != 0);
    if ((threadIdx.x & 31) == 0) bits[e >> 5] = b;
}

__global__ void cvt_all_kernel(
    const float* __restrict__ p0, const float* __restrict__ p1,
    const float* __restrict__ p2, const float* __restrict__ p3,
    const float* __restrict__ p4, const float* __restrict__ p5,
    __nv_bfloat16* __restrict__ q0, __nv_bfloat16* __restrict__ q1,
    __nv_bfloat16* __restrict__ q2, __nv_bfloat16* __restrict__ q3,
    __nv_bfloat16* __restrict__ q4, __nv_bfloat16* __restrict__ q5)
{
    const int a = blockIdx.y;
    const float* in  = (a == 0) ? p0 : (a == 1) ? p1 : (a == 2) ? p2
                     : (a == 3) ? p3 : (a == 4) ? p4 : p5;
    __nv_bfloat16* out = (a == 0) ? q0 : (a == 1) ? q1 : (a == 2) ? q2
                       : (a == 3) ? q3 : (a == 4) ? q4 : q5;
    const int n4 = (a < 3) ? (M_TOTAL * PK / 4) : (OUTD * PK / 4);
    for (int i = blockIdx.x * 256 + threadIdx.x; i < n4; i += gridDim.x * 256) {
        const float4 v = *(const float4*)(in + (size_t)i * 4);
        __nv_bfloat16* o = out + (size_t)i * 4;
        *(__nv_bfloat162*)(o)     = __nv_bfloat162(__float2bfloat16(v.x), __float2bfloat16(v.y));
        *(__nv_bfloat162*)(o + 2) = __nv_bfloat162(__float2bfloat16(v.z), __float2bfloat16(v.w));
    }
}

// ---------------- projection: raw mma.sync, out[(n,h,s,d)] = relu(X@W^T+b) ------
// 128x128 CTA tile, 8 warps (32x64 warp tile), K chunks of 64, 2-stage cp.async.
#define PR_AS   72                 // bf16 elems per smem row (144B, conflict-free)
#define PR_STGA (128 * PR_AS)      // elems per A (or B) tile
#define PR_STG  (2 * PR_STGA)      // elems per stage (A+B)
#define PR_NCH  (PK / 64)          // 16
#define PR_SMEM (2 * PR_STG * 2 > 128 * 132 * 4 ? 2 * PR_STG * 2 : 128 * 132 * 4)

__global__ __launch_bounds__(256, 2) void proj_kernel(
    const __nv_bfloat16* __restrict__ X0, const __nv_bfloat16* __restrict__ X1,
    const __nv_bfloat16* __restrict__ X2,
    const __nv_bfloat16* __restrict__ W0, const __nv_bfloat16* __restrict__ W1,
    const __nv_bfloat16* __restrict__ W2,
    const float* __restrict__ b0, const float* __restrict__ b1,
    const float* __restrict__ b2,
    __nv_bfloat16* __restrict__ o0, __nv_bfloat16* __restrict__ o1,
    __nv_bfloat16* __restrict__ o2)
{
    const int z = blockIdx.z;
    const __nv_bfloat16* X = (z == 0) ? X0 : (z == 1) ? X1 : X2;
    const __nv_bfloat16* W = (z == 0) ? W0 : (z == 1) ? W1 : W2;
    const float*      bias = (z == 0) ? b0 : (z == 1) ? b1 : b2;
    __nv_bfloat16*     out = (z == 0) ? o0 : (z == 1) ? o1 : o2;

    extern __shared__ char smraw[];
    __nv_bfloat16* sm16 = (__nv_bfloat16*)smraw;
    float* Cs = (float*)smraw;
    const unsigned sbase = (unsigned)__cvta_generic_to_shared(smraw);

    const int tid    = threadIdx.x;
    const int warp   = tid >> 5;
    const int lane   = tid & 31;
    const int warp_m = warp >> 1;    // 0..3
    const int warp_n = warp & 1;     // 0..1
    const int rowBase = blockIdx.y * 128;
    const int colBase = blockIdx.x * 128;

    const __nv_bfloat16* Ag = X + (size_t)rowBase * PK;
    const __nv_bfloat16* Bg = W + (size_t)colBase * PK;

    float c[2][8][4];
    #pragma unroll
    for (int i = 0; i < 2; i++)
        #pragma unroll
        for (int j = 0; j < 8; j++)
            #pragma unroll
            for (int q = 0; q < 4; q++) c[i][j][q] = 0.f;

    // fill one stage (A 128x64 + B 128x64 bf16)
    auto fill = [&](int s, int ck) {
        __nv_bfloat16* As = sm16 + s * PR_STG;
        __nv_bfloat16* Bs = As + PR_STGA;
        const __nv_bfloat16* Ac = Ag + ck * 64;
        const __nv_bfloat16* Bc = Bg + ck * 64;
        #pragma unroll
        for (int it = 0; it < 4; it++) {
            const int f = tid + 256 * it;     // 1024 chunks of 16B each (A and B)
            const int row = f >> 3;
            const int ch  = f & 7;
            cp16(As + row * PR_AS + ch * 8, Ac + (size_t)row * PK + ch * 8);
            cp16(Bs + row * PR_AS + ch * 8, Bc + (size_t)row * PK + ch * 8);
        }
    };

    fill(0, 0); CP_COMMIT();
    fill(1, 1); CP_COMMIT();

    const int arow_off = lane & 15;
    const int acol_off = (lane >> 4) << 3;
    const int krow_off = (lane & 7) + ((lane >> 4) << 3);
    const int kcol_off = lane & 8;

    for (int ck = 0; ck < PR_NCH; ck++) {
        const int s = ck & 1;
        CP_WAIT(1);
        __syncthreads();

        const unsigned abase = sbase + (unsigned)(s * PR_STG) * 2;
        const unsigned bbase = abase + (unsigned)PR_STGA * 2;

        #pragma unroll
        for (int k16 = 0; k16 < 4; k16++) {
            unsigned a0[4], a1[4];
            ldsm_x4(a0, abase + (unsigned)(((warp_m * 32 + arow_off) * PR_AS
                                            + k16 * 16 + acol_off) * 2));
            ldsm_x4(a1, abase + (unsigned)(((warp_m * 32 + 16 + arow_off) * PR_AS
                                            + k16 * 16 + acol_off) * 2));
            #pragma unroll
            for (int nb = 0; nb < 4; nb++) {
                unsigned b[4];
                ldsm_x4(b, bbase + (unsigned)(((warp_n * 64 + nb * 16 + krow_off) * PR_AS
                                               + k16 * 16 + kcol_off) * 2));
                mma16816(c[0][2 * nb],     a0, b[0], b[1]);
                mma16816(c[0][2 * nb + 1], a0, b[2], b[3]);
                mma16816(c[1][2 * nb],     a1, b[0], b[1]);
                mma16816(c[1][2 * nb + 1], a1, b[2], b[3]);
            }
        }
        __syncthreads();
        if (ck + 2 < PR_NCH) { fill(s, ck + 2); CP_COMMIT(); }
    }

    // epilogue: stage fp32 C to smem, then bias+relu+bf16 scatter
    const int r0  = lane >> 2;
    const int lq2 = (lane & 3) * 2;
    #pragma unroll
    for (int i = 0; i < 2; i++) {
        const int row = warp_m * 32 + i * 16 + r0;
        #pragma unroll
        for (int j = 0; j < 8; j++) {
            const int col = warp_n * 64 + j * 8 + lq2;
            Cs[row * 132 + col]       = c[i][j][0];
            Cs[row * 132 + col + 1]   = c[i][j][1];
            Cs[(row + 8) * 132 + col]     = c[i][j][2];
            Cs[(row + 8) * 132 + col + 1] = c[i][j][3];
        }
    }
    __syncthreads();

    const int h = colBase >> 7;
    #pragma unroll
    for (int it = 0; it < 16; it++) {
        const int f   = tid + 256 * it;      // 4096 float4s over 128x128
        const int row = f >> 5;
        const int c4  = (f & 31) * 4;
        float4 v = *(const float4*)(Cs + row * 132 + c4);
        const float4 bv = *(const float4*)(bias + colBase + c4);
        v.x = fmaxf(v.x + bv.x, 0.f);
        v.y = fmaxf(v.y + bv.y, 0.f);
        v.z = fmaxf(v.z + bv.z, 0.f);
        v.w = fmaxf(v.w + bv.w, 0.f);
        const int m  = rowBase + row;
        const int nb = m >> 11;
        const int sq = m & 2047;
        __nv_bfloat16* op = out + (((size_t)(nb * HEADS + h)) * SEQ + sq) * HEAD_D + c4;
        *(__nv_bfloat162*)(op)     = __nv_bfloat162(__float2bfloat16(v.x), __float2bfloat16(v.y));
        *(__nv_bfloat162*)(op + 2) = __nv_bfloat162(__float2bfloat16(v.z), __float2bfloat16(v.w));
    }
}

// ---------------- attention: register-resident FA2-style, BKV=128 ---------------
#define BQ    128
#define BKV   128
#define QSTR  136          // bf16 row stride: 272B, ldmatrix conflict-free
#define NT    (SEQ / BKV)  // 16
#define OSTR  132

__global__ __launch_bounds__(256, 1) void attn_kernel(
    const __nv_bfloat16* __restrict__ Q, const __nv_bfloat16* __restrict__ K,
    const __nv_bfloat16* __restrict__ V, const unsigned* __restrict__ mbits,
    float* __restrict__ out)
{
    extern __shared__ char smraw[];
    __nv_bfloat16* Qs  = (__nv_bfloat16*)smraw;      // 128 x QSTR
    __nv_bfloat16* KV0 = Qs + BQ * QSTR;             // 2 stages x (K 128xQSTR, V 128xQSTR)
    float*         Os  = (float*)KV0;                // epilogue staging

    const int tid  = threadIdx.x;
    const int warp = tid >> 5;
    const int lane = tid & 31;
    const int nb = blockIdx.z;
    const int h  = blockIdx.y;
    const int qt = blockIdx.x;
    const int q0 = qt * BQ;

    const __nv_bfloat16* Qg = Q + (((size_t)(nb * HEADS + h)) * SEQ + q0) * HEAD_D;
    const __nv_bfloat16* Kg = K + (((size_t)(nb * HEADS + h)) * SEQ) * HEAD_D;
    const __nv_bfloat16* Vg = V + (((size_t)(nb * HEADS + h)) * SEQ) * HEAD_D;

    // async load Q (group 0)
    #pragma unroll
    for (int it = 0; it < 8; it++) {
        const int f = tid + 256 * it;
        const int row = f >> 4;
        const int c8 = (f & 15) * 8;
        cp16(Qs + row * QSTR + c8, Qg + row * HEAD_D + c8);
    }
    CP_COMMIT();

    // async load K/V stage 0 (group 1): 128 rows each
    {
        __nv_bfloat16* Ks0 = KV0;
        __nv_bfloat16* Vs0 = KV0 + BKV * QSTR;
        #pragma unroll
        for (int it = 0; it < 8; it++) {
            const int f = tid + 256 * it;      // 2048 chunks each
            const int row = f >> 4;
            const int c8 = (f & 15) * 8;
            cp16(Ks0 + row * QSTR + c8, Kg + row * HEAD_D + c8);
            cp16(Vs0 + row * QSTR + c8, Vg + row * HEAD_D + c8);
        }
    }
    CP_COMMIT();

    CP_WAIT(1);
    __syncthreads();

    // persistent Q A-fragments
    const unsigned qbase = (unsigned)__cvta_generic_to_shared(Qs);
    unsigned qa[8][4];
    {
        const int qrow = warp * 16 + (lane & 15);
        const int qco  = (lane >> 4) << 3;
        #pragma unroll
        for (int d8 = 0; d8 < 8; d8++)
            ldsm_x4(qa[d8], qbase + (unsigned)((qrow * QSTR + d8 * 16 + qco) * 2));
    }

    float oacc[16][4];
    #pragma unroll
    for (int j = 0; j < 16; j++) {
        #pragma unroll
        for (int q = 0; q < 4; q++) oacc[j][q] = 0.f;
    }
    float li0 = 0.f;
    float li1 = 0.f;

    const float scale = 0.08838834764831845f;
    const int lq2 = (lane & 3) * 2;
    const int r0  = lane >> 2;
    const unsigned* mrow0 = mbits + (size_t)(q0 + warp * 16 + r0) * (SEQ / 32);
    const unsigned* mrow1 = mrow0 + 8 * (SEQ / 32);

    const int krow_off = (lane & 7) + ((lane >> 4) << 3);
    const int kcol_off = lane & 8;
    const int vrow_off = lane & 15;
    const int vcol_off = (lane >> 4) << 3;

    for (int kt = 0; kt < NT; kt++) {
        const int st = kt & 1;
        __syncthreads();   // all warps done reading stage st^1
        if (kt + 1 < NT) {
            __nv_bfloat16* Kn = KV0 + (st ^ 1) * 2 * BKV * QSTR;
            __nv_bfloat16* Vn = Kn + BKV * QSTR;
            const __nv_bfloat16* Kt = Kg + (size_t)(kt + 1) * BKV * HEAD_D;
            const __nv_bfloat16* Vt = Vg + (size_t)(kt + 1) * BKV * HEAD_D;
            #pragma unroll
            for (int it = 0; it < 8; it++) {
                const int f = tid + 256 * it;
                const int row = f >> 4;
                const int c8 = (f & 15) * 8;
                cp16(Kn + row * QSTR + c8, Kt + row * HEAD_D + c8);
                cp16(Vn + row * QSTR + c8, Vt + row * HEAD_D + c8);
            }
            CP_COMMIT();
            CP_WAIT(1);
        } else {
            CP_WAIT(0);
        }
        __syncthreads();   // stage st visible

        // prefetch this tile's mask words early (hide L2 latency under mma)
        unsigned mw0[4], mw1[4];
        #pragma unroll
        for (int w = 0; w < 4; w++) {
            mw0[w] = mrow0[kt * 4 + w];
            mw1[w] = mrow1[kt * 4 + w];
        }

        __nv_bfloat16* Ks = KV0 + st * 2 * BKV * QSTR;
        __nv_bfloat16* Vs = Ks + BKV * QSTR;
        const unsigned kbase = (unsigned)__cvta_generic_to_shared(Ks);
        const unsigned vbase = (unsigned)__cvta_generic_to_shared(Vs);

        // S = Q @ K^T (16 x 128 per warp), registers only
        float sacc[16][4];
        #pragma unroll
        for (int j = 0; j < 16; j++) {
            #pragma unroll
            for (int q = 0; q < 4; q++) sacc[j][q] = 0.f;
        }

        #pragma unroll
        for (int d8 = 0; d8 < 8; d8++) {
            #pragma unroll
            for (int jp = 0; jp < 8; jp++) {
                unsigned b[4];
                ldsm_x4(b, kbase + (unsigned)(((jp * 16 + krow_off) * QSTR
                                               + d8 * 16 + kcol_off) * 2));
                mma16816(sacc[2 * jp],     qa[d8], b[0], b[1]);
                mma16816(sacc[2 * jp + 1], qa[d8], b[2], b[3]);
            }
        }

        // mask + exp in registers; accumulate partial row sums
        #pragma unroll
        for (int j = 0; j < 16; j++) {
            const int sh = ((j & 3) * 8 + lq2);
            const unsigned wa = mw0[j >> 2];
            const unsigned wb = mw1[j >> 2];
            const float e0 = ((wa >> sh) & 1u)       ? __expf(sacc[j][0] * scale) : 0.f;
            const float e1 = ((wa >> (sh + 1)) & 1u) ? __expf(sacc[j][1] * scale) : 0.f;
            const float e2 = ((wb >> sh) & 1u)       ? __expf(sacc[j][2] * scale) : 0.f;
            const float e3 = ((wb >> (sh + 1)) & 1u) ? __expf(sacc[j][3] * scale) : 0.f;
            sacc[j][0] = e0;
            sacc[j][1] = e1;
            sacc[j][2] = e2;
            sacc[j][3] = e3;
            li0 += e0 + e1;
            li1 += e2 + e3;
        }

        // O += P @ V
        #pragma unroll
        for (int kk = 0; kk < 8; kk++) {
            unsigned pa[4];
            pa[0] = packbf(sacc[2 * kk][0],     sacc[2 * kk][1]);
            pa[1] = packbf(sacc[2 * kk][2],     sacc[2 * kk][3]);
            pa[2] = packbf(sacc[2 * kk + 1][0], sacc[2 * kk + 1][1]);
            pa[3] = packbf(sacc[2 * kk + 1][2], sacc[2 * kk + 1][3]);
            #pragma unroll
            for (int dp = 0; dp < 8; dp++) {
                unsigned v[4];
                ldsm_x4t(v, vbase + (unsigned)(((kk * 16 + vrow_off) * QSTR
                                                + dp * 16 + vcol_off) * 2));
                mma16816(oacc[2 * dp],     pa, v[0], v[1]);
                mma16816(oacc[2 * dp + 1], pa, v[2], v[3]);
            }
        }
    }

    __syncthreads();   // all warps done with KV smem before O staging overwrites it

    // reduce row sums across the quad
    li0 += __shfl_xor_sync(0xffffffffu, li0, 1);
    li0 += __shfl_xor_sync(0xffffffffu, li0, 2);
    li1 += __shfl_xor_sync(0xffffffffu, li1, 1);
    li1 += __shfl_xor_sync(0xffffffffu, li1, 2);
    const float inv0 = 1.0f / li0;
    const float inv1 = 1.0f / li1;

    {
        float* o0 = Os + (warp * 16 + r0) * OSTR + lq2;
        float* o1 = o0 + 8 * OSTR;
        #pragma unroll
        for (int dj = 0; dj < 16; dj++) {
            o0[dj * 8 + 0] = oacc[dj][0] * inv0;
            o0[dj * 8 + 1] = oacc[dj][1] * inv0;
            o1[dj * 8 + 0] = oacc[dj][2] * inv1;
            o1[dj * 8 + 1] = oacc[dj][3] * inv1;
        }
    }
    __syncthreads();

    #pragma unroll
    for (int it = 0; it < 16; it++) {
        const int f   = tid + 256 * it;
        const int row = f >> 5;
        const int c4  = (f & 31) * 4;
        const float4 v = *(const float4*)(Os + row * OSTR + c4);
        const int s = q0 + row;
        *(float4*)(out + ((size_t)nb * SEQ + s) * OUTD + h * HEAD_D + c4) = v;
    }
}

// ---------------- launch --------------------------------------------------------
extern "C" void kernel_launch(void* const* d_in, const int* in_sizes, int n_in,
                              void* d_out, int out_size)
{
    const float* query = (const float*)d_in[0];
    const float* key   = (const float*)d_in[1];
    const float* value = (const float*)d_in[2];
    const int*   mask  = (const int*)d_in[3];
    const float* Wq    = (const float*)d_in[4];
    const float* bq    = (const float*)d_in[5];
    const float* Wk    = (const float*)d_in[6];
    const float* bk    = (const float*)d_in[7];
    const float* Wv    = (const float*)d_in[8];
    const float* bv    = (const float*)d_in[9];
    float* out = (float*)d_out;

    __nv_bfloat16 *qb = 0, *kb = 0, *vb = 0, *xb = 0, *wb = 0;
    unsigned* mb = 0;
    cudaGetSymbolAddress((void**)&qb, g_Q);
    cudaGetSymbolAddress((void**)&kb, g_K);
    cudaGetSymbolAddress((void**)&vb, g_V);
    cudaGetSymbolAddress((void**)&xb, g_Xb);
    cudaGetSymbolAddress((void**)&wb, g_Wb);
    cudaGetSymbolAddress((void**)&mb, g_mbits);

    const size_t XN = (size_t)M_TOTAL * PK;
    const size_t WN = (size_t)OUTD * PK;
    __nv_bfloat16* Xb0 = xb;
    __nv_bfloat16* Xb1 = xb + XN;
    __nv_bfloat16* Xb2 = xb + 2 * XN;
    __nv_bfloat16* Wb0 = wb;
    __nv_bfloat16* Wb1 = wb + WN;
    __nv_bfloat16* Wb2 = wb + 2 * WN;

    dim3 cgrid(512, 6);
    cvt_all_kernel<<<cgrid, 256>>>(query, key, value, Wq, Wk, Wv,
                                   Xb0, Xb1, Xb2, Wb0, Wb1, Wb2);
    pack_mask_kernel<<<(SEQ * SEQ) / 256, 256>>>(mask, mb);

    const int proj_smem = PR_SMEM;   // max(2 stages, epilogue staging)
    cudaFuncSetAttribute(proj_kernel, cudaFuncAttributeMaxDynamicSharedMemorySize,
                         proj_smem);
    dim3 pgrid(OUTD / 128, M_TOTAL / 128, 3);
    proj_kernel<<<pgrid, 256, proj_smem>>>(Xb0, Xb1, Xb2, Wb0, Wb1, Wb2,
                                           bq, bk, bv, qb, kb, vb);

    const int attn_smem = (BQ * QSTR + 4 * BKV * QSTR) * 2;   // 174080
    cudaFuncSetAttribute(attn_kernel, cudaFuncAttributeMaxDynamicSharedMemorySize,
                         attn_smem);
    dim3 agrid(SEQ / BQ, HEADS, NB);
    attn_kernel<<<agrid, 256, attn_smem>>>(qb, kb, vb, mb, out);
}

// round 10
// speedup vs baseline: 8.2457x; 1.0199x over previous
#include <cuda_runtime.h>
#include <cuda_bf16.h>
#include <cstdint>
#include <math.h>

#define EMB     1024
#define HEADS   16
#define HEAD_D  128
#define NB      2
#define SEQ     2048
#define OUTD    (HEADS * HEAD_D)   // 2048
#define M_TOTAL (NB * SEQ)         // 4096
#define PK      EMB

// ---------------- scratch ------------------------------------------------------
__device__ __nv_bfloat16 g_Q[(size_t)NB * HEADS * SEQ * HEAD_D];
__device__ __nv_bfloat16 g_K[(size_t)NB * HEADS * SEQ * HEAD_D];
__device__ __nv_bfloat16 g_V[(size_t)NB * HEADS * SEQ * HEAD_D];
__device__ __nv_bfloat16 g_Xb[(size_t)3 * M_TOTAL * PK];
__device__ __nv_bfloat16 g_Wb[(size_t)3 * OUTD * PK];
__device__ unsigned      g_mbits[SEQ * (SEQ / 32)];

__device__ __forceinline__ void cp16(void* dst, const void* src) {
    unsigned d = (unsigned)__cvta_generic_to_shared(dst);
    asm volatile("cp.async.cg.shared.global [%0], [%1], 16;\n" :: "r"(d), "l"(src));
}
#define CP_COMMIT() asm volatile("cp.async.commit_group;\n" ::: "memory")
#define CP_WAIT(k)  asm volatile("cp.async.wait_group %0;\n" :: "n"(k) : "memory")

__device__ __forceinline__ void ldsm_x4(unsigned* r, unsigned addr) {
    asm volatile("ldmatrix.sync.aligned.m8n8.x4.shared.b16 {%0,%1,%2,%3}, [%4];"
        : "=r"(r[0]), "=r"(r[1]), "=r"(r[2]), "=r"(r[3]) : "r"(addr));
}
__device__ __forceinline__ void ldsm_x4t(unsigned* r, unsigned addr) {
    asm volatile("ldmatrix.sync.aligned.m8n8.x4.trans.shared.b16 {%0,%1,%2,%3}, [%4];"
        : "=r"(r[0]), "=r"(r[1]), "=r"(r[2]), "=r"(r[3]) : "r"(addr));
}
__device__ __forceinline__ void mma16816(float* c, const unsigned* a,
                                         unsigned b0, unsigned b1) {
    asm volatile(
        "mma.sync.aligned.m16n8k16.row.col.f32.bf16.bf16.f32 "
        "{%0,%1,%2,%3}, {%4,%5,%6,%7}, {%8,%9}, {%0,%1,%2,%3};"
        : "+f"(c[0]), "+f"(c[1]), "+f"(c[2]), "+f"(c[3])
        : "r"(a[0]), "r"(a[1]), "r"(a[2]), "r"(a[3]), "r"(b0), "r"(b1));
}
__device__ __forceinline__ unsigned packbf(float lo, float hi) {
    unsigned d;
    asm("cvt.rn.bf16x2.f32 %0, %1, %2;" : "=r"(d) : "f"(hi), "f"(lo));
    return d;
}

// ---------------- helpers ------------------------------------------------------
__global__ void pack_mask_kernel(const int* __restrict__ mask, unsigned* __restrict__ bits)
{
    const int e = blockIdx.x * 256 + threadIdx.x;
    const unsigned b = __ballot_sync(0xffffffffu, mask[e] != 0);
    if ((threadIdx.x & 31) == 0) bits[e >> 5] = b;
}

__global__ void cvt_all_kernel(
    const float* __restrict__ p0, const float* __restrict__ p1,
    const float* __restrict__ p2, const float* __restrict__ p3,
    const float* __restrict__ p4, const float* __restrict__ p5,
    __nv_bfloat16* __restrict__ q0, __nv_bfloat16* __restrict__ q1,
    __nv_bfloat16* __restrict__ q2, __nv_bfloat16* __restrict__ q3,
    __nv_bfloat16* __restrict__ q4, __nv_bfloat16* __restrict__ q5)
{
    const int a = blockIdx.y;
    const float* in  = (a == 0) ? p0 : (a == 1) ? p1 : (a == 2) ? p2
                     : (a == 3) ? p3 : (a == 4) ? p4 : p5;
    __nv_bfloat16* out = (a == 0) ? q0 : (a == 1) ? q1 : (a == 2) ? q2
                       : (a == 3) ? q3 : (a == 4) ? q4 : q5;
    const int n4 = (a < 3) ? (M_TOTAL * PK / 4) : (OUTD * PK / 4);
    for (int i = blockIdx.x * 256 + threadIdx.x; i < n4; i += gridDim.x * 256) {
        const float4 v = *(const float4*)(in + (size_t)i * 4);
        __nv_bfloat16* o = out + (size_t)i * 4;
        *(__nv_bfloat162*)(o)     = __nv_bfloat162(__float2bfloat16(v.x), __float2bfloat16(v.y));
        *(__nv_bfloat162*)(o + 2) = __nv_bfloat162(__float2bfloat16(v.z), __float2bfloat16(v.w));
    }
}

// ---------------- projection: raw mma.sync (unchanged from R9) ------------------
#define PR_AS   72
#define PR_STGA (128 * PR_AS)
#define PR_STG  (2 * PR_STGA)
#define PR_NCH  (PK / 64)
#define PR_SMEM (2 * PR_STG * 2 > 128 * 132 * 4 ? 2 * PR_STG * 2 : 128 * 132 * 4)

__global__ __launch_bounds__(256, 2) void proj_kernel(
    const __nv_bfloat16* __restrict__ X0, const __nv_bfloat16* __restrict__ X1,
    const __nv_bfloat16* __restrict__ X2,
    const __nv_bfloat16* __restrict__ W0, const __nv_bfloat16* __restrict__ W1,
    const __nv_bfloat16* __restrict__ W2,
    const float* __restrict__ b0, const float* __restrict__ b1,
    const float* __restrict__ b2,
    __nv_bfloat16* __restrict__ o0, __nv_bfloat16* __restrict__ o1,
    __nv_bfloat16* __restrict__ o2)
{
    const int z = blockIdx.z;
    const __nv_bfloat16* X = (z == 0) ? X0 : (z == 1) ? X1 : X2;
    const __nv_bfloat16* W = (z == 0) ? W0 : (z == 1) ? W1 : W2;
    const float*      bias = (z == 0) ? b0 : (z == 1) ? b1 : b2;
    __nv_bfloat16*     out = (z == 0) ? o0 : (z == 1) ? o1 : o2;

    extern __shared__ char smraw[];
    __nv_bfloat16* sm16 = (__nv_bfloat16*)smraw;
    float* Cs = (float*)smraw;
    const unsigned sbase = (unsigned)__cvta_generic_to_shared(smraw);

    const int tid    = threadIdx.x;
    const int warp   = tid >> 5;
    const int lane   = tid & 31;
    const int warp_m = warp >> 1;
    const int warp_n = warp & 1;
    const int rowBase = blockIdx.y * 128;
    const int colBase = blockIdx.x * 128;

    const __nv_bfloat16* Ag = X + (size_t)rowBase * PK;
    const __nv_bfloat16* Bg = W + (size_t)colBase * PK;

    float c[2][8][4];
    #pragma unroll
    for (int i = 0; i < 2; i++)
        #pragma unroll
        for (int j = 0; j < 8; j++)
            #pragma unroll
            for (int q = 0; q < 4; q++) c[i][j][q] = 0.f;

    auto fill = [&](int s, int ck) {
        __nv_bfloat16* As = sm16 + s * PR_STG;
        __nv_bfloat16* Bs = As + PR_STGA;
        const __nv_bfloat16* Ac = Ag + ck * 64;
        const __nv_bfloat16* Bc = Bg + ck * 64;
        #pragma unroll
        for (int it = 0; it < 4; it++) {
            const int f = tid + 256 * it;
            const int row = f >> 3;
            const int ch  = f & 7;
            cp16(As + row * PR_AS + ch * 8, Ac + (size_t)row * PK + ch * 8);
            cp16(Bs + row * PR_AS + ch * 8, Bc + (size_t)row * PK + ch * 8);
        }
    };

    fill(0, 0); CP_COMMIT();
    fill(1, 1); CP_COMMIT();

    const int arow_off = lane & 15;
    const int acol_off = (lane >> 4) << 3;
    const int krow_off = (lane & 7) + ((lane >> 4) << 3);
    const int kcol_off = lane & 8;

    for (int ck = 0; ck < PR_NCH; ck++) {
        const int s = ck & 1;
        CP_WAIT(1);
        __syncthreads();

        const unsigned abase = sbase + (unsigned)(s * PR_STG) * 2;
        const unsigned bbase = abase + (unsigned)PR_STGA * 2;

        #pragma unroll
        for (int k16 = 0; k16 < 4; k16++) {
            unsigned a0[4], a1[4];
            ldsm_x4(a0, abase + (unsigned)(((warp_m * 32 + arow_off) * PR_AS
                                            + k16 * 16 + acol_off) * 2));
            ldsm_x4(a1, abase + (unsigned)(((warp_m * 32 + 16 + arow_off) * PR_AS
                                            + k16 * 16 + acol_off) * 2));
            #pragma unroll
            for (int nb = 0; nb < 4; nb++) {
                unsigned b[4];
                ldsm_x4(b, bbase + (unsigned)(((warp_n * 64 + nb * 16 + krow_off) * PR_AS
                                               + k16 * 16 + kcol_off) * 2));
                mma16816(c[0][2 * nb],     a0, b[0], b[1]);
                mma16816(c[0][2 * nb + 1], a0, b[2], b[3]);
                mma16816(c[1][2 * nb],     a1, b[0], b[1]);
                mma16816(c[1][2 * nb + 1], a1, b[2], b[3]);
            }
        }
        __syncthreads();
        if (ck + 2 < PR_NCH) { fill(s, ck + 2); CP_COMMIT(); }
    }

    const int r0  = lane >> 2;
    const int lq2 = (lane & 3) * 2;
    #pragma unroll
    for (int i = 0; i < 2; i++) {
        const int row = warp_m * 32 + i * 16 + r0;
        #pragma unroll
        for (int j = 0; j < 8; j++) {
            const int col = warp_n * 64 + j * 8 + lq2;
            Cs[row * 132 + col]       = c[i][j][0];
            Cs[row * 132 + col + 1]   = c[i][j][1];
            Cs[(row + 8) * 132 + col]     = c[i][j][2];
            Cs[(row + 8) * 132 + col + 1] = c[i][j][3];
        }
    }
    __syncthreads();

    const int h = colBase >> 7;
    #pragma unroll
    for (int it = 0; it < 16; it++) {
        const int f   = tid + 256 * it;
        const int row = f >> 5;
        const int c4  = (f & 31) * 4;
        float4 v = *(const float4*)(Cs + row * 132 + c4);
        const float4 bv = *(const float4*)(bias + colBase + c4);
        v.x = fmaxf(v.x + bv.x, 0.f);
        v.y = fmaxf(v.y + bv.y, 0.f);
        v.z = fmaxf(v.z + bv.z, 0.f);
        v.w = fmaxf(v.w + bv.w, 0.f);
        const int m  = rowBase + row;
        const int nb = m >> 11;
        const int sq = m & 2047;
        __nv_bfloat16* op = out + (((size_t)(nb * HEADS + h)) * SEQ + sq) * HEAD_D + c4;
        *(__nv_bfloat162*)(op)     = __nv_bfloat162(__float2bfloat16(v.x), __float2bfloat16(v.y));
        *(__nv_bfloat162*)(op + 2) = __nv_bfloat162(__float2bfloat16(v.z), __float2bfloat16(v.w));
    }
}

// ---------------- attention: 128 threads, BQ=64, 2 CTAs/SM ----------------------
#define BQ    64
#define BKV   64
#define QSTR  136          // bf16 row stride: 272B, ldmatrix conflict-free
#define NT    (SEQ / BKV)  // 32
#define OSTR  132
#define ATHR  128

__global__ __launch_bounds__(ATHR, 2) void attn_kernel(
    const __nv_bfloat16* __restrict__ Q, const __nv_bfloat16* __restrict__ K,
    const __nv_bfloat16* __restrict__ V, const unsigned* __restrict__ mbits,
    float* __restrict__ out)
{
    extern __shared__ char smraw[];
    __nv_bfloat16* Qs  = (__nv_bfloat16*)smraw;      // 64 x QSTR
    __nv_bfloat16* KV0 = Qs + BQ * QSTR;             // 2 stages x (K 64xQSTR, V 64xQSTR)
    float*         Os  = (float*)KV0;                // epilogue staging (64 x OSTR)

    const int tid  = threadIdx.x;
    const int warp = tid >> 5;        // 0..3
    const int lane = tid & 31;
    const int nb = blockIdx.z;
    const int h  = blockIdx.y;
    const int qt = blockIdx.x;
    const int q0 = qt * BQ;

    const __nv_bfloat16* Qg = Q + (((size_t)(nb * HEADS + h)) * SEQ + q0) * HEAD_D;
    const __nv_bfloat16* Kg = K + (((size_t)(nb * HEADS + h)) * SEQ) * HEAD_D;
    const __nv_bfloat16* Vg = V + (((size_t)(nb * HEADS + h)) * SEQ) * HEAD_D;

    // async load Q (group 0): 64 x 128 bf16 = 1024 16B chunks
    #pragma unroll
    for (int it = 0; it < 8; it++) {
        const int f = tid + ATHR * it;
        const int row = f >> 4;
        const int c8 = (f & 15) * 8;
        cp16(Qs + row * QSTR + c8, Qg + row * HEAD_D + c8);
    }
    CP_COMMIT();

    // async load K/V stage 0 (group 1)
    {
        __nv_bfloat16* Ks0 = KV0;
        __nv_bfloat16* Vs0 = KV0 + BKV * QSTR;
        #pragma unroll
        for (int it = 0; it < 8; it++) {
            const int f = tid + ATHR * it;
            const int row = f >> 4;
            const int c8 = (f & 15) * 8;
            cp16(Ks0 + row * QSTR + c8, Kg + row * HEAD_D + c8);
            cp16(Vs0 + row * QSTR + c8, Vg + row * HEAD_D + c8);
        }
    }
    CP_COMMIT();

    CP_WAIT(1);          // Q arrived
    __syncthreads();

    // persistent Q A-fragments (warp -> rows warp*16..+16)
    const unsigned qbase = (unsigned)__cvta_generic_to_shared(Qs);
    unsigned qa[8][4];
    {
        const int qrow = warp * 16 + (lane & 15);
        const int qco  = (lane >> 4) << 3;
        #pragma unroll
        for (int d8 = 0; d8 < 8; d8++)
            ldsm_x4(qa[d8], qbase + (unsigned)((qrow * QSTR + d8 * 16 + qco) * 2));
    }

    float oacc[16][4];
    #pragma unroll
    for (int j = 0; j < 16; j++) {
        #pragma unroll
        for (int q = 0; q < 4; q++) oacc[j][q] = 0.f;
    }
    float li0 = 0.f;
    float li1 = 0.f;

    const float scale = 0.08838834764831845f;
    const int lq2 = (lane & 3) * 2;
    const int r0  = lane >> 2;
    const unsigned* mrow0 = mbits + (size_t)(q0 + warp * 16 + r0) * (SEQ / 32);
    const unsigned* mrow1 = mrow0 + 8 * (SEQ / 32);

    const int krow_off = (lane & 7) + ((lane >> 4) << 3);
    const int kcol_off = lane & 8;
    const int vrow_off = lane & 15;
    const int vcol_off = (lane >> 4) << 3;

    for (int kt = 0; kt < NT; kt++) {
        const int st = kt & 1;
        __syncthreads();   // all warps done reading stage st^1
        if (kt + 1 < NT) {
            __nv_bfloat16* Kn = KV0 + (st ^ 1) * 2 * BKV * QSTR;
            __nv_bfloat16* Vn = Kn + BKV * QSTR;
            const __nv_bfloat16* Kt = Kg + (size_t)(kt + 1) * BKV * HEAD_D;
            const __nv_bfloat16* Vt = Vg + (size_t)(kt + 1) * BKV * HEAD_D;
            #pragma unroll
            for (int it = 0; it < 8; it++) {
                const int f = tid + ATHR * it;
                const int row = f >> 4;
                const int c8 = (f & 15) * 8;
                cp16(Kn + row * QSTR + c8, Kt + row * HEAD_D + c8);
                cp16(Vn + row * QSTR + c8, Vt + row * HEAD_D + c8);
            }
            CP_COMMIT();
            CP_WAIT(1);
        } else {
            CP_WAIT(0);
        }
        __syncthreads();   // stage st visible

        // prefetch this tile's mask words (hide L2 latency under mma)
        const unsigned w00 = mrow0[kt * 2];
        const unsigned w01 = mrow0[kt * 2 + 1];
        const unsigned w10 = mrow1[kt * 2];
        const unsigned w11 = mrow1[kt * 2 + 1];

        __nv_bfloat16* Ks = KV0 + st * 2 * BKV * QSTR;
        __nv_bfloat16* Vs = Ks + BKV * QSTR;
        const unsigned kbase = (unsigned)__cvta_generic_to_shared(Ks);
        const unsigned vbase = (unsigned)__cvta_generic_to_shared(Vs);

        // S = Q @ K^T (16 x 64 per warp), registers only
        float sacc[8][4];
        #pragma unroll
        for (int j = 0; j < 8; j++) {
            #pragma unroll
            for (int q = 0; q < 4; q++) sacc[j][q] = 0.f;
        }

        #pragma unroll
        for (int d8 = 0; d8 < 8; d8++) {
            #pragma unroll
            for (int jp = 0; jp < 4; jp++) {
                unsigned b[4];
                ldsm_x4(b, kbase + (unsigned)(((jp * 16 + krow_off) * QSTR
                                               + d8 * 16 + kcol_off) * 2));
                mma16816(sacc[2 * jp],     qa[d8], b[0], b[1]);
                mma16816(sacc[2 * jp + 1], qa[d8], b[2], b[3]);
            }
        }

        // mask + exp in registers; accumulate partial row sums
        #pragma unroll
        for (int j = 0; j < 8; j++) {
            const int sh = (j * 8 + lq2) & 31;
            const unsigned wa = (j < 4) ? w00 : w01;
            const unsigned wb = (j < 4) ? w10 : w11;
            const float e0 = ((wa >> sh) & 1u)       ? __expf(sacc[j][0] * scale) : 0.f;
            const float e1 = ((wa >> (sh + 1)) & 1u) ? __expf(sacc[j][1] * scale) : 0.f;
            const float e2 = ((wb >> sh) & 1u)       ? __expf(sacc[j][2] * scale) : 0.f;
            const float e3 = ((wb >> (sh + 1)) & 1u) ? __expf(sacc[j][3] * scale) : 0.f;
            sacc[j][0] = e0;
            sacc[j][1] = e1;
            sacc[j][2] = e2;
            sacc[j][3] = e3;
            li0 += e0 + e1;
            li1 += e2 + e3;
        }

        // O += P @ V
        #pragma unroll
        for (int kk = 0; kk < 4; kk++) {
            unsigned pa[4];
            pa[0] = packbf(sacc[2 * kk][0],     sacc[2 * kk][1]);
            pa[1] = packbf(sacc[2 * kk][2],     sacc[2 * kk][3]);
            pa[2] = packbf(sacc[2 * kk + 1][0], sacc[2 * kk + 1][1]);
            pa[3] = packbf(sacc[2 * kk + 1][2], sacc[2 * kk + 1][3]);
            #pragma unroll
            for (int dp = 0; dp < 8; dp++) {
                unsigned v[4];
                ldsm_x4t(v, vbase + (unsigned)(((kk * 16 + vrow_off) * QSTR
                                                + dp * 16 + vcol_off) * 2));
                mma16816(oacc[2 * dp],     pa, v[0], v[1]);
                mma16816(oacc[2 * dp + 1], pa, v[2], v[3]);
            }
        }
    }

    __syncthreads();   // all warps done with KV smem before O staging overwrites it

    // reduce row sums across the quad
    li0 += __shfl_xor_sync(0xffffffffu, li0, 1);
    li0 += __shfl_xor_sync(0xffffffffu, li0, 2);
    li1 += __shfl_xor_sync(0xffffffffu, li1, 1);
    li1 += __shfl_xor_sync(0xffffffffu, li1, 2);
    const float inv0 = 1.0f / li0;
    const float inv1 = 1.0f / li1;

    // normalize + stage to smem, coalesced write
    {
        float* o0 = Os + (warp * 16 + r0) * OSTR + lq2;
        float* o1 = o0 + 8 * OSTR;
        #pragma unroll
        for (int dj = 0; dj < 16; dj++) {
            o0[dj * 8 + 0] = oacc[dj][0] * inv0;
            o0[dj * 8 + 1] = oacc[dj][1] * inv0;
            o1[dj * 8 + 0] = oacc[dj][2] * inv1;
            o1[dj * 8 + 1] = oacc[dj][3] * inv1;
        }
    }
    __syncthreads();

    #pragma unroll
    for (int it = 0; it < 16; it++) {
        const int f   = tid + ATHR * it;     // 2048 float4s over 64x128
        const int row = f >> 5;
        const int c4  = (f & 31) * 4;
        const float4 v = *(const float4*)(Os + row * OSTR + c4);
        const int s = q0 + row;
        *(float4*)(out + ((size_t)nb * SEQ + s) * OUTD + h * HEAD_D + c4) = v;
    }
}

// ---------------- launch --------------------------------------------------------
extern "C" void kernel_launch(void* const* d_in, const int* in_sizes, int n_in,
                              void* d_out, int out_size)
{
    const float* query = (const float*)d_in[0];
    const float* key   = (const float*)d_in[1];
    const float* value = (const float*)d_in[2];
    const int*   mask  = (const int*)d_in[3];
    const float* Wq    = (const float*)d_in[4];
    const float* bq    = (const float*)d_in[5];
    const float* Wk    = (const float*)d_in[6];
    const float* bk    = (const float*)d_in[7];
    const float* Wv    = (const float*)d_in[8];
    const float* bv    = (const float*)d_in[9];
    float* out = (float*)d_out;

    __nv_bfloat16 *qb = 0, *kb = 0, *vb = 0, *xb = 0, *wb = 0;
    unsigned* mb = 0;
    cudaGetSymbolAddress((void**)&qb, g_Q);
    cudaGetSymbolAddress((void**)&kb, g_K);
    cudaGetSymbolAddress((void**)&vb, g_V);
    cudaGetSymbolAddress((void**)&xb, g_Xb);
    cudaGetSymbolAddress((void**)&wb, g_Wb);
    cudaGetSymbolAddress((void**)&mb, g_mbits);

    const size_t XN = (size_t)M_TOTAL * PK;
    const size_t WN = (size_t)OUTD * PK;
    __nv_bfloat16* Xb0 = xb;
    __nv_bfloat16* Xb1 = xb + XN;
    __nv_bfloat16* Xb2 = xb + 2 * XN;
    __nv_bfloat16* Wb0 = wb;
    __nv_bfloat16* Wb1 = wb + WN;
    __nv_bfloat16* Wb2 = wb + 2 * WN;

    dim3 cgrid(512, 6);
    cvt_all_kernel<<<cgrid, 256>>>(query, key, value, Wq, Wk, Wv,
                                   Xb0, Xb1, Xb2, Wb0, Wb1, Wb2);
    pack_mask_kernel<<<(SEQ * SEQ) / 256, 256>>>(mask, mb);

    const int proj_smem = PR_SMEM;
    cudaFuncSetAttribute(proj_kernel, cudaFuncAttributeMaxDynamicSharedMemorySize,
                         proj_smem);
    dim3 pgrid(OUTD / 128, M_TOTAL / 128, 3);
    proj_kernel<<<pgrid, 256, proj_smem>>>(Xb0, Xb1, Xb2, Wb0, Wb1, Wb2,
                                           bq, bk, bv, qb, kb, vb);

    // attn smem: Q (64 x QSTR) + 2 stages x (K+V = 128 rows x QSTR), bf16
    const int attn_smem = (BQ * QSTR + 4 * BKV * QSTR) * 2;   // 87040
    cudaFuncSetAttribute(attn_kernel, cudaFuncAttributeMaxDynamicSharedMemorySize,
                         attn_smem);
    dim3 agrid(SEQ / BQ, HEADS, NB);
    attn_kernel<<<agrid, ATHR, attn_smem>>>(qb, kb, vb, mb, out);
}